// round 1
// baseline (speedup 1.0000x reference)
#include <cuda_runtime.h>

// MultiHeadDenseSynthesizer: B=64, L=500, F=256, H=4, dk=64
// out = LN( softmax( relu((q Wq)_h W1 + b1) W2 + b2 ) (v Wv)_h  @ fc_w + q )

#define BB  64
#define LL  500
#define FF  256
#define HH  4
#define DKK 64
#define BLL (BB*LL)

// scratch (device globals are the sanctioned alloc-free workaround)
__device__ float g_wt[BB*HH*LL*DKK];   // relu(qh@w1+b1), [b,h,l,d]
__device__ float g_vh[BB*HH*LL*DKK];   // v projection,   [b,h,l,d]
__device__ float g_ctx[BLL*FF];        // attn output,    [b,l,h*d]

__device__ __forceinline__ void fma16(float c[4][4], const float* __restrict__ a,
                                      const float* __restrict__ w) {
    float4 a4 = *(const float4*)a;
    float4 w4 = *(const float4*)w;
    float av[4] = {a4.x, a4.y, a4.z, a4.w};
    float wv[4] = {w4.x, w4.y, w4.z, w4.w};
#pragma unroll
    for (int i = 0; i < 4; i++)
#pragma unroll
        for (int j = 0; j < 4; j++)
            c[i][j] = fmaf(av[i], wv[j], c[i][j]);
}

// ---------------------------------------------------------------------------
// Kernel 1: projections. grid (500, 4, 2), 256 thr.
//   z=0: qp tile [64x64] -> fused weight = relu(qp @ w1 + b1) -> g_wt
//   z=1: vp tile -> g_vh
// N-tile (64) == dk, so each CTA's output tile is exactly one head's slice.
// ---------------------------------------------------------------------------
__global__ void __launch_bounds__(256)
k_proj(const float* __restrict__ qin, const float* __restrict__ vin,
       const float* __restrict__ w_qs, const float* __restrict__ w_vs,
       const float* __restrict__ w1, const float* __restrict__ b1)
{
    extern __shared__ float sm[];
    float* As  = sm;                 // [32][68] A^T tile
    float* Ws  = As + 32*68;         // [32][68]
    float* Cs  = Ws + 32*68;         // [64][68] C^T (qh feature-major)
    float* W1s = Cs + 64*68;         // [64][68]

    const int mode = blockIdx.z;
    const float* A = mode ? vin : qin;
    const float* W = mode ? w_vs : w_qs;
    const int m0 = blockIdx.x * 64;
    const int h  = blockIdx.y;
    const int n0 = h * 64;
    const int tid = threadIdx.x;
    const int tx = tid & 15, ty = tid >> 4;

    float c[4][4] = {};
    for (int k0 = 0; k0 < FF; k0 += 32) {
        {
            int kk = tid & 31, rb = tid >> 5;
#pragma unroll
            for (int r = rb; r < 64; r += 8)
                As[kk*68 + r] = A[(m0 + r)*FF + k0 + kk];
        }
        {
            int nn = tid & 63, kb = tid >> 6;
#pragma unroll
            for (int k = kb; k < 32; k += 4)
                Ws[k*68 + nn] = W[(k0 + k)*FF + n0 + nn];
        }
        __syncthreads();
#pragma unroll 8
        for (int k = 0; k < 32; k++)
            fma16(c, &As[k*68 + ty*4], &Ws[k*68 + tx*4]);
        __syncthreads();
    }

    if (mode) {
#pragma unroll
        for (int i = 0; i < 4; i++) {
            int gm = m0 + ty*4 + i;
            int b = gm / LL, l = gm - b*LL;
            float* dst = &g_vh[((b*HH + h)*LL + l)*DKK + tx*4];
#pragma unroll
            for (int j = 0; j < 4; j++) dst[j] = c[i][j];
        }
        return;
    }

    // stage qh tile transposed (contract over this head's 64 features)
#pragma unroll
    for (int i = 0; i < 4; i++)
#pragma unroll
        for (int j = 0; j < 4; j++)
            Cs[(tx*4 + j)*68 + ty*4 + i] = c[i][j];
    {
        int dd = tid & 63, kb = tid >> 6;
#pragma unroll
        for (int k = kb; k < 64; k += 4)
            W1s[k*68 + dd] = w1[k*DKK + dd];
    }
    __syncthreads();

    float c2[4][4];
#pragma unroll
    for (int i = 0; i < 4; i++)
#pragma unroll
        for (int j = 0; j < 4; j++)
            c2[i][j] = b1[tx*4 + j];
#pragma unroll 8
    for (int k = 0; k < 64; k++)
        fma16(c2, &Cs[k*68 + ty*4], &W1s[k*68 + tx*4]);

#pragma unroll
    for (int i = 0; i < 4; i++) {
        int gm = m0 + ty*4 + i;
        int b = gm / LL, l = gm - b*LL;
        float* dst = &g_wt[((b*HH + h)*LL + l)*DKK + tx*4];
#pragma unroll
        for (int j = 0; j < 4; j++) dst[j] = fmaxf(c2[i][j], 0.f);
    }
}

// ---------------------------------------------------------------------------
// Kernel 2: dense-synthesizer attention, single-pass softmax (no max needed:
// logits ~ N(0, 0.7)). grid (8, H, B), 256 thr, 64 rows x 64-col j-chunks.
// out[r,:] = sum_j exp(s_rj) vh[j,:] ;  denom[r] = sum_j exp(s_rj)
// ---------------------------------------------------------------------------
__global__ void __launch_bounds__(256)
k_attn(const float* __restrict__ w2, const float* __restrict__ b2)
{
    extern __shared__ float sm[];
    float* WtT   = sm;               // [64][68]  weight^T (k-major)
    float* W2s   = WtT + 64*68;      // [64][68]  w2 chunk [k][j]
    float* PsT   = W2s + 64*68;      // [64][68]  P^T (j-major)
    float* Vs    = PsT + 64*68;      // [64][68]  vh chunk [j][d]
    float* red   = Vs  + 64*68;      // [64][16]  denom partials
    float* denom = red + 64*16;      // [64]

    const int r0 = blockIdx.x * 64;
    const int h  = blockIdx.y, b = blockIdx.z;
    const int bh = b*HH + h;
    const int tid = threadIdx.x;
    const int tx = tid & 15, ty = tid >> 4;

    {
        int kk = tid & 63, rb = tid >> 6;
#pragma unroll
        for (int r = rb; r < 64; r += 4) {
            int row = r0 + r;
            WtT[kk*68 + r] = (row < LL) ? g_wt[(bh*LL + row)*DKK + kk] : 0.f;
        }
    }

    float o[4][4] = {};
    float dp[4] = {};

    for (int j0 = 0; j0 < LL; j0 += 64) {
        __syncthreads();   // prev GEMM2 done with W2s/Vs/PsT (1st iter: WtT visible after next sync)
        {
            int jj = tid & 63, kb = tid >> 6;
#pragma unroll
            for (int k = kb; k < 64; k += 4) {
                int j = j0 + jj;
                W2s[k*68 + jj] = (j < LL) ? w2[k*LL + j] : 0.f;
            }
            int dd = tid & 63, jb = tid >> 6;
#pragma unroll
            for (int jl = jb; jl < 64; jl += 4) {
                int j = j0 + jl;
                Vs[jl*68 + dd] = (j < LL) ? g_vh[(bh*LL + j)*DKK + dd] : 0.f;
            }
        }
        __syncthreads();

        // S = weight @ w2 + b2
        float s[4][4];
#pragma unroll
        for (int i = 0; i < 4; i++)
#pragma unroll
            for (int j = 0; j < 4; j++) {
                int jg = j0 + tx*4 + j;
                s[i][j] = (jg < LL) ? b2[jg] : 0.f;
            }
#pragma unroll 8
        for (int k = 0; k < 64; k++)
            fma16(s, &WtT[k*68 + ty*4], &W2s[k*68 + tx*4]);

        // P = exp(S) (masked), store transposed, track denom partials
#pragma unroll
        for (int i = 0; i < 4; i++)
#pragma unroll
            for (int j = 0; j < 4; j++) {
                int jg = j0 + tx*4 + j;
                float p = (jg < LL) ? __expf(s[i][j]) : 0.f;
                dp[i] += p;
                PsT[(tx*4 + j)*68 + ty*4 + i] = p;
            }
        __syncthreads();

        // out += P @ vh_chunk
#pragma unroll 8
        for (int k = 0; k < 64; k++)
            fma16(o, &PsT[k*68 + ty*4], &Vs[k*68 + tx*4]);
    }

    __syncthreads();
#pragma unroll
    for (int i = 0; i < 4; i++)
        red[(ty*4 + i)*16 + tx] = dp[i];
    __syncthreads();
    if (tid < 64) {
        float ss = 0.f;
#pragma unroll
        for (int t = 0; t < 16; t++) ss += red[tid*16 + t];
        denom[tid] = ss;
    }
    __syncthreads();

#pragma unroll
    for (int i = 0; i < 4; i++) {
        int row = r0 + ty*4 + i;
        if (row >= LL) continue;
        float inv = 1.f / denom[ty*4 + i];
        float* dst = &g_ctx[(b*LL + row)*FF + h*DKK + tx*4];
#pragma unroll
        for (int j = 0; j < 4; j++) dst[j] = o[i][j] * inv;
    }
}

// ---------------------------------------------------------------------------
// Kernel 3: out = LN(ctx @ fc_w + q). grid 2000 (16 rows/CTA), 256 thr.
// Full N=256 per CTA so LayerNorm completes in-kernel.
// ---------------------------------------------------------------------------
__global__ void __launch_bounds__(256)
k_final(const float* __restrict__ qin, const float* __restrict__ fcw,
        const float* __restrict__ lng, const float* __restrict__ lnb,
        float* __restrict__ out)
{
    extern __shared__ float sm[];
    float* As = sm;            // [32][20]
    float* Wc = As + 32*20;    // [32][256]
    float* Rs = Wc;            // alias after GEMM: [16][260]

    const int m0 = blockIdx.x * 16;
    const int tid = threadIdx.x;
    const int tx = tid & 63, ty = tid >> 6;

    float c[4][4] = {};
    for (int k0 = 0; k0 < FF; k0 += 32) {
        {
            int kk = tid & 31, r2 = tid >> 5;      // r2: 0..7
            As[kk*20 + r2]     = g_ctx[(m0 + r2)*FF + k0 + kk];
            As[kk*20 + r2 + 8] = g_ctx[(m0 + r2 + 8)*FF + k0 + kk];
        }
#pragma unroll
        for (int kk = 0; kk < 32; kk++)
            Wc[kk*256 + tid] = fcw[(k0 + kk)*FF + tid];
        __syncthreads();
#pragma unroll 8
        for (int k = 0; k < 32; k++)
            fma16(c, &As[k*20 + ty*4], &Wc[k*256 + tx*4]);
        __syncthreads();
    }

    // residual add, stage rows in smem
#pragma unroll
    for (int i = 0; i < 4; i++) {
        int gr = m0 + ty*4 + i;
#pragma unroll
        for (int j = 0; j < 4; j++)
            Rs[(ty*4 + i)*260 + tx*4 + j] = c[i][j] + qin[gr*FF + tx*4 + j];
    }
    __syncthreads();

    // LayerNorm: warp w handles rows 2w, 2w+1
    int warp = tid >> 5, lane = tid & 31;
#pragma unroll
    for (int rr = warp*2; rr < warp*2 + 2; rr++) {
        float vals[8];
        float sum = 0.f, sq = 0.f;
#pragma unroll
        for (int t = 0; t < 8; t++) {
            float x = Rs[rr*260 + lane + t*32];
            vals[t] = x; sum += x; sq += x*x;
        }
#pragma unroll
        for (int off = 16; off; off >>= 1) {
            sum += __shfl_xor_sync(0xffffffffu, sum, off);
            sq  += __shfl_xor_sync(0xffffffffu, sq,  off);
        }
        float mu  = sum * (1.f/256.f);
        float var = sq * (1.f/256.f) - mu*mu;
        float rstd = rsqrtf(var + 1e-6f);
        int gr = m0 + rr;
#pragma unroll
        for (int t = 0; t < 8; t++) {
            int cI = lane + t*32;
            out[gr*FF + cI] = (vals[t] - mu) * rstd * lng[cI] + lnb[cI];
        }
    }
}

// ---------------------------------------------------------------------------
extern "C" void kernel_launch(void* const* d_in, const int* in_sizes, int n_in,
                              void* d_out, int out_size)
{
    const float* q    = (const float*)d_in[0];
    // d_in[1] (k) is unused by the reference model
    const float* v    = (const float*)d_in[2];
    const float* w_qs = (const float*)d_in[3];
    const float* w_vs = (const float*)d_in[4];
    const float* w1   = (const float*)d_in[5];
    const float* b1   = (const float*)d_in[6];
    const float* w2   = (const float*)d_in[7];
    const float* b2   = (const float*)d_in[8];
    const float* fcw  = (const float*)d_in[9];
    const float* lng  = (const float*)d_in[10];
    const float* lnb  = (const float*)d_in[11];
    float* out = (float*)d_out;

    const int SM1 = (32*68*2 + 64*68*2) * 4;            // 52224 B
    const int SM3 = (64*68*4 + 64*16 + 64) * 4;         // 73984 B
    const int SM4 = (32*20 + 32*256) * 4;               // 35328 B
    cudaFuncSetAttribute(k_proj,  cudaFuncAttributeMaxDynamicSharedMemorySize, SM1);
    cudaFuncSetAttribute(k_attn,  cudaFuncAttributeMaxDynamicSharedMemorySize, SM3);
    cudaFuncSetAttribute(k_final, cudaFuncAttributeMaxDynamicSharedMemorySize, SM4);

    k_proj <<<dim3(BLL/64, HH, 2),        256, SM1>>>(q, v, w_qs, w_vs, w1, b1);
    k_attn <<<dim3((LL+63)/64, HH, BB),   256, SM3>>>(w2, b2);
    k_final<<<BLL/16,                     256, SM4>>>(q, fcw, lng, lnb, out);
}

// round 3
// speedup vs baseline: 1.4715x; 1.4715x over previous
#include <cuda_runtime.h>
#include <cuda_bf16.h>
#include <cstdint>

// MultiHeadDenseSynthesizer: B=64, L=500, F=256, H=4, dk=64
// Round 3: attention via mma.sync bf16 (split hi/lo, 3-term), register-resident
// P hand-off (S accum frag == P A-frag). No tcgen05 (harness targets sm_103 base).

#define BB  64
#define LL  500
#define FF  256
#define HH  4
#define DKK 64
#define BLL (BB*LL)
#define BH  (BB*HH)
#define LPAD 512

// ---------------- device scratch (uint4 for 16B alignment; zero-initialized) --
__device__ float g_ctx[BLL*FF];
__device__ uint4 g_wt_h4[BH*LL*DKK/8],   g_wt_l4[BH*LL*DKK/8];    // W  [bh][l][d]
__device__ uint4 g_vT_h4[BH*DKK*LPAD/8], g_vT_l4[BH*DKK*LPAD/8];  // Vt [bh][d][j]
__device__ uint4 g_w2T_h4[LPAD*DKK/8],   g_w2T_l4[LPAD*DKK/8];    // w2T [j][d]

__device__ __forceinline__ uint32_t pack_bf2(__nv_bfloat16 a, __nv_bfloat16 b) {
    return (uint32_t)__bfloat16_as_ushort(a) | ((uint32_t)__bfloat16_as_ushort(b) << 16);
}

__device__ __forceinline__ void mma16816(float c[4], const uint32_t a[4], const uint32_t b[2]) {
    asm volatile(
        "mma.sync.aligned.m16n8k16.row.col.f32.bf16.bf16.f32 "
        "{%0,%1,%2,%3}, {%4,%5,%6,%7}, {%8,%9}, {%0,%1,%2,%3};"
        : "+f"(c[0]), "+f"(c[1]), "+f"(c[2]), "+f"(c[3])
        : "r"(a[0]), "r"(a[1]), "r"(a[2]), "r"(a[3]), "r"(b[0]), "r"(b[1]));
}

__device__ __forceinline__ void fma16(float c[4][4], const float* __restrict__ a,
                                      const float* __restrict__ w) {
    float4 a4 = *(const float4*)a;
    float4 w4 = *(const float4*)w;
    float av[4] = {a4.x, a4.y, a4.z, a4.w};
    float wv[4] = {w4.x, w4.y, w4.z, w4.w};
#pragma unroll
    for (int i = 0; i < 4; i++)
#pragma unroll
        for (int j = 0; j < 4; j++)
            c[i][j] = fmaf(av[i], wv[j], c[i][j]);
}

// ---------------------------------------------------------------------------
// k_prep: w2 [64,500] -> w2T hi/lo [512,64] bf16 (zero rows 500..511)
// ---------------------------------------------------------------------------
__global__ void k_prep(const float* __restrict__ w2)
{
    __nv_bfloat16* w2h = (__nv_bfloat16*)g_w2T_h4;
    __nv_bfloat16* w2l = (__nv_bfloat16*)g_w2T_l4;
    int idx = blockIdx.x * 256 + threadIdx.x;   // 512*64 = 32768
    int j = idx >> 6, d = idx & 63;
    float v = (j < LL) ? w2[d*LL + j] : 0.f;
    __nv_bfloat16 h = __float2bfloat16(v);
    float r = v - __bfloat162float(h);
    w2h[j*DKK + d] = h;
    w2l[j*DKK + d] = __float2bfloat16(r);
}

// ---------------------------------------------------------------------------
// Kernel 1: projections (fp32 GEMM, bf16 hi/lo epilogues). grid (500,4,2).
// ---------------------------------------------------------------------------
__global__ void __launch_bounds__(256)
k_proj(const float* __restrict__ qin, const float* __restrict__ vin,
       const float* __restrict__ w_qs, const float* __restrict__ w_vs,
       const float* __restrict__ w1, const float* __restrict__ b1)
{
    extern __shared__ float sm[];
    float* As  = sm;                 // [32][68]
    float* Ws  = As + 32*68;         // [32][68]
    float* Cs  = Ws + 32*68;         // [64][68]
    float* W1s = Cs + 64*68;         // [64][68]

    const int mode = blockIdx.z;
    const float* A = mode ? vin : qin;
    const float* W = mode ? w_vs : w_qs;
    const int m0 = blockIdx.x * 64;
    const int h  = blockIdx.y;
    const int n0 = h * 64;
    const int tid = threadIdx.x;
    const int tx = tid & 15, ty = tid >> 4;

    float c[4][4] = {};
    for (int k0 = 0; k0 < FF; k0 += 32) {
        {
            int kk = tid & 31, rb = tid >> 5;
#pragma unroll
            for (int r = rb; r < 64; r += 8)
                As[kk*68 + r] = A[(m0 + r)*FF + k0 + kk];
        }
        {
            int nn = tid & 63, kb = tid >> 6;
#pragma unroll
            for (int k = kb; k < 32; k += 4)
                Ws[k*68 + nn] = W[(k0 + k)*FF + n0 + nn];
        }
        __syncthreads();
#pragma unroll 8
        for (int k = 0; k < 32; k++)
            fma16(c, &As[k*68 + ty*4], &Ws[k*68 + tx*4]);
        __syncthreads();
    }

    if (mode) {
        // stage transposed: Cs[d][l_local]
#pragma unroll
        for (int i = 0; i < 4; i++)
#pragma unroll
            for (int j = 0; j < 4; j++)
                Cs[(tx*4 + j)*68 + ty*4 + i] = c[i][j];
        __syncthreads();
        __nv_bfloat16* vTh = (__nv_bfloat16*)g_vT_h4;
        __nv_bfloat16* vTl = (__nv_bfloat16*)g_vT_l4;
        int w = tid >> 5, ln = tid & 31;
#pragma unroll
        for (int dq = 0; dq < 8; dq++) {
            int dd = w*8 + dq;
            float v0 = Cs[dd*68 + 2*ln];
            float v1 = Cs[dd*68 + 2*ln + 1];
            int gm0 = m0 + 2*ln;
            int b0 = gm0 / LL, p0 = gm0 - b0*LL;
            int gm1 = gm0 + 1;
            int b1_ = gm1 / LL, p1 = gm1 - b1_*LL;
            __nv_bfloat16 h0 = __float2bfloat16(v0), h1 = __float2bfloat16(v1);
            __nv_bfloat16 e0 = __float2bfloat16(v0 - __bfloat162float(h0));
            __nv_bfloat16 e1 = __float2bfloat16(v1 - __bfloat162float(h1));
            size_t a0 = ((size_t)((b0*HH + h)*DKK + dd))*LPAD + p0;
            if (b0 == b1_) {
                *(uint32_t*)(vTh + a0) = pack_bf2(h0, h1);
                *(uint32_t*)(vTl + a0) = pack_bf2(e0, e1);
            } else {
                size_t a1 = ((size_t)((b1_*HH + h)*DKK + dd))*LPAD + p1;
                vTh[a0] = h0; vTh[a1] = h1;
                vTl[a0] = e0; vTl[a1] = e1;
            }
        }
        return;
    }

    // qh @ w1 + b1, relu -> bf16 hi/lo
#pragma unroll
    for (int i = 0; i < 4; i++)
#pragma unroll
        for (int j = 0; j < 4; j++)
            Cs[(tx*4 + j)*68 + ty*4 + i] = c[i][j];
    {
        int dd = tid & 63, kb = tid >> 6;
#pragma unroll
        for (int k = kb; k < 64; k += 4)
            W1s[k*68 + dd] = w1[k*DKK + dd];
    }
    __syncthreads();

    float c2[4][4];
#pragma unroll
    for (int i = 0; i < 4; i++)
#pragma unroll
        for (int j = 0; j < 4; j++)
            c2[i][j] = b1[tx*4 + j];
#pragma unroll 8
    for (int k = 0; k < 64; k++)
        fma16(c2, &Cs[k*68 + ty*4], &W1s[k*68 + tx*4]);

    __nv_bfloat16* wth = (__nv_bfloat16*)g_wt_h4;
    __nv_bfloat16* wtl = (__nv_bfloat16*)g_wt_l4;
#pragma unroll
    for (int i = 0; i < 4; i++) {
        int gm = m0 + ty*4 + i;
        int b = gm / LL, l = gm - b*LL;
        size_t base = ((size_t)((b*HH + h)*LL + l))*DKK + tx*4;
        uint32_t hw[2], lw[2];
#pragma unroll
        for (int jj = 0; jj < 2; jj++) {
            float x0 = fmaxf(c2[i][jj*2], 0.f);
            float x1 = fmaxf(c2[i][jj*2 + 1], 0.f);
            __nv_bfloat16 h0 = __float2bfloat16(x0), h1 = __float2bfloat16(x1);
            __nv_bfloat16 e0 = __float2bfloat16(x0 - __bfloat162float(h0));
            __nv_bfloat16 e1 = __float2bfloat16(x1 - __bfloat162float(h1));
            hw[jj] = pack_bf2(h0, h1);
            lw[jj] = pack_bf2(e0, e1);
        }
        uint2 u; u.x = hw[0]; u.y = hw[1];
        *(uint2*)(wth + base) = u;
        u.x = lw[0]; u.y = lw[1];
        *(uint2*)(wtl + base) = u;
    }
}

// ---------------------------------------------------------------------------
// Kernel 2: mma.sync attention. grid (8, H, B), 128 threads (4 warps x m16).
// Per chunk (64 cols): S = W @ w2T^T (3-term split, fp32 accum in regs),
// P = exp(S+b2) masked -> re-packed in regs as A-frag, O += P @ vT^T.
// Denominator: per-thread accumulation + 2x shfl.
// ---------------------------------------------------------------------------
#define SPITCH 144   // bytes per smem row (64 bf16 = 128B data + 16B pad)

__global__ void __launch_bounds__(128)
k_attn_mma(const float* __restrict__ b2)
{
    __shared__ float b2s[64];
    __shared__ __align__(16) char sW2h[64*SPITCH];
    __shared__ __align__(16) char sW2l[64*SPITCH];
    __shared__ __align__(16) char sVh [64*SPITCH];
    __shared__ __align__(16) char sVl [64*SPITCH];

    const int tid  = threadIdx.x;
    const int lane = tid & 31, wid = tid >> 5;
    const int g4 = lane >> 2, t4 = lane & 3;
    const int l0 = blockIdx.x * 64;
    const int h  = blockIdx.y, b = blockIdx.z;
    const int bh = b*HH + h;
    const int r0 = l0 + wid*16 + g4;          // this thread's row (and r0+8)

    const __nv_bfloat16* wth = (const __nv_bfloat16*)g_wt_h4;
    const __nv_bfloat16* wtl = (const __nv_bfloat16*)g_wt_l4;

    // ---- A-frags for W (whole k=64), hi/lo, register-resident
    uint32_t aWh[4][4], aWl[4][4];
    {
        const bool v0 = (r0 < LL), v1 = (r0 + 8 < LL);
        size_t base0 = (size_t)(bh*LL + r0)*DKK;
        size_t base1 = (size_t)(bh*LL + r0 + 8)*DKK;
#pragma unroll
        for (int kt = 0; kt < 4; kt++) {
            int c0 = kt*16 + t4*2, c8 = c0 + 8;
            aWh[kt][0] = v0 ? *(const uint32_t*)(wth + base0 + c0) : 0u;
            aWh[kt][1] = v1 ? *(const uint32_t*)(wth + base1 + c0) : 0u;
            aWh[kt][2] = v0 ? *(const uint32_t*)(wth + base0 + c8) : 0u;
            aWh[kt][3] = v1 ? *(const uint32_t*)(wth + base1 + c8) : 0u;
            aWl[kt][0] = v0 ? *(const uint32_t*)(wtl + base0 + c0) : 0u;
            aWl[kt][1] = v1 ? *(const uint32_t*)(wtl + base1 + c0) : 0u;
            aWl[kt][2] = v0 ? *(const uint32_t*)(wtl + base0 + c8) : 0u;
            aWl[kt][3] = v1 ? *(const uint32_t*)(wtl + base1 + c8) : 0u;
        }
    }

    float oacc[8][4];
#pragma unroll
    for (int nt = 0; nt < 8; nt++)
#pragma unroll
        for (int e = 0; e < 4; e++) oacc[nt][e] = 0.f;
    float dp0 = 0.f, dp1 = 0.f;

    const int jq = 0;  // silence unused warnings pattern (no-op)
    (void)jq;

    for (int c = 0; c < 8; c++) {
        const int j0 = c * 64;
        __syncthreads();   // previous iteration done reading smem

        // ---- stage chunk operands: w2T rows j0..j0+63, vT cols j0..j0+63
#pragma unroll
        for (int it = 0; it < 4; it++) {
            int idx = tid + it*128;            // 0..511
            int row = idx >> 3, gq = idx & 7;
            *(uint4*)(sW2h + row*SPITCH + gq*16) = g_w2T_h4[(size_t)(j0 + row)*8 + gq];
            *(uint4*)(sW2l + row*SPITCH + gq*16) = g_w2T_l4[(size_t)(j0 + row)*8 + gq];
            size_t sv = (size_t)(bh*DKK + row)*(LPAD/8) + (j0 >> 3) + gq;
            *(uint4*)(sVh + row*SPITCH + gq*16) = g_vT_h4[sv];
            *(uint4*)(sVl + row*SPITCH + gq*16) = g_vT_l4[sv];
        }
        if (tid < 64) b2s[tid] = (j0 + tid < LL) ? b2[j0 + tid] : 0.f;
        __syncthreads();

        // ---- S = W @ w2T^T (accum fp32), 3-term split
        float sacc[8][4];
#pragma unroll
        for (int nt = 0; nt < 8; nt++)
#pragma unroll
            for (int e = 0; e < 4; e++) sacc[nt][e] = 0.f;

#pragma unroll
        for (int kt = 0; kt < 4; kt++) {
#pragma unroll
            for (int nt = 0; nt < 8; nt++) {
                int off = (nt*8 + g4)*SPITCH + (kt*16 + t4*2)*2;
                uint32_t bh2[2], bl2[2];
                bh2[0] = *(const uint32_t*)(sW2h + off);
                bh2[1] = *(const uint32_t*)(sW2h + off + 16);
                bl2[0] = *(const uint32_t*)(sW2l + off);
                bl2[1] = *(const uint32_t*)(sW2l + off + 16);
                mma16816(sacc[nt], aWh[kt], bh2);
                mma16816(sacc[nt], aWh[kt], bl2);
                mma16816(sacc[nt], aWl[kt], bh2);
            }
        }

        // ---- P = exp(S + b2), masked; repack as A-frags (hi/lo)
        uint32_t phA[4][4], plA[4][4];
#pragma unroll
        for (int nt = 0; nt < 8; nt++) {
            int jl = nt*8 + t4*2;
            int jg = j0 + jl;
            float bb0 = b2s[jl], bb1 = b2s[jl + 1];
            float p0 = (jg     < LL) ? __expf(sacc[nt][0] + bb0) : 0.f;
            float p1 = (jg + 1 < LL) ? __expf(sacc[nt][1] + bb1) : 0.f;
            float p2 = (jg     < LL) ? __expf(sacc[nt][2] + bb0) : 0.f;
            float p3 = (jg + 1 < LL) ? __expf(sacc[nt][3] + bb1) : 0.f;
            dp0 += p0 + p1;
            dp1 += p2 + p3;
            __nv_bfloat16 h0 = __float2bfloat16(p0), h1 = __float2bfloat16(p1);
            __nv_bfloat16 h2 = __float2bfloat16(p2), h3 = __float2bfloat16(p3);
            __nv_bfloat16 e0 = __float2bfloat16(p0 - __bfloat162float(h0));
            __nv_bfloat16 e1 = __float2bfloat16(p1 - __bfloat162float(h1));
            __nv_bfloat16 e2 = __float2bfloat16(p2 - __bfloat162float(h2));
            __nv_bfloat16 e3 = __float2bfloat16(p3 - __bfloat162float(h3));
            int kt = nt >> 1;
            int i0 = (nt & 1) ? 2 : 0;
            phA[kt][i0]     = pack_bf2(h0, h1);
            phA[kt][i0 + 1] = pack_bf2(h2, h3);
            plA[kt][i0]     = pack_bf2(e0, e1);
            plA[kt][i0 + 1] = pack_bf2(e2, e3);
        }

        // ---- O += P @ vT^T, 3-term split
#pragma unroll
        for (int kt = 0; kt < 4; kt++) {
#pragma unroll
            for (int nt = 0; nt < 8; nt++) {
                int off = (nt*8 + g4)*SPITCH + (kt*16 + t4*2)*2;
                uint32_t bvh[2], bvl[2];
                bvh[0] = *(const uint32_t*)(sVh + off);
                bvh[1] = *(const uint32_t*)(sVh + off + 16);
                bvl[0] = *(const uint32_t*)(sVl + off);
                bvl[1] = *(const uint32_t*)(sVl + off + 16);
                mma16816(oacc[nt], phA[kt], bvh);
                mma16816(oacc[nt], phA[kt], bvl);
                mma16816(oacc[nt], plA[kt], bvh);
            }
        }
    }

    // ---- softmax denominators: reduce over the 4 lanes sharing each row
    dp0 += __shfl_xor_sync(0xffffffffu, dp0, 1);
    dp0 += __shfl_xor_sync(0xffffffffu, dp0, 2);
    dp1 += __shfl_xor_sync(0xffffffffu, dp1, 1);
    dp1 += __shfl_xor_sync(0xffffffffu, dp1, 2);
    float inv0 = 1.f / dp0, inv1 = 1.f / dp1;

    // ---- store context rows
    if (r0 < LL) {
        float* dst = g_ctx + ((size_t)(b*LL + r0))*FF + h*DKK + t4*2;
#pragma unroll
        for (int nt = 0; nt < 8; nt++) {
            float2 v; v.x = oacc[nt][0]*inv0; v.y = oacc[nt][1]*inv0;
            *(float2*)(dst + nt*8) = v;
        }
    }
    if (r0 + 8 < LL) {
        float* dst = g_ctx + ((size_t)(b*LL + r0 + 8))*FF + h*DKK + t4*2;
#pragma unroll
        for (int nt = 0; nt < 8; nt++) {
            float2 v; v.x = oacc[nt][2]*inv1; v.y = oacc[nt][3]*inv1;
            *(float2*)(dst + nt*8) = v;
        }
    }
}

// ---------------------------------------------------------------------------
// Kernel 3: out = LN(ctx @ fc_w + q). grid 2000 (16 rows/CTA), 256 thr.
// ---------------------------------------------------------------------------
__global__ void __launch_bounds__(256)
k_final(const float* __restrict__ qin, const float* __restrict__ fcw,
        const float* __restrict__ lng, const float* __restrict__ lnb,
        float* __restrict__ out)
{
    extern __shared__ float sm[];
    float* As = sm;            // [32][20]
    float* Wc = As + 32*20;    // [32][256]
    float* Rs = Wc;            // alias after GEMM: [16][260]

    const int m0 = blockIdx.x * 16;
    const int tid = threadIdx.x;
    const int tx = tid & 63, ty = tid >> 6;

    float c[4][4] = {};
    for (int k0 = 0; k0 < FF; k0 += 32) {
        {
            int kk = tid & 31, r2 = tid >> 5;
            As[kk*20 + r2]     = g_ctx[(m0 + r2)*FF + k0 + kk];
            As[kk*20 + r2 + 8] = g_ctx[(m0 + r2 + 8)*FF + k0 + kk];
        }
#pragma unroll
        for (int kk = 0; kk < 32; kk++)
            Wc[kk*256 + tid] = fcw[(k0 + kk)*FF + tid];
        __syncthreads();
#pragma unroll 8
        for (int k = 0; k < 32; k++)
            fma16(c, &As[k*20 + ty*4], &Wc[k*256 + tx*4]);
        __syncthreads();
    }

#pragma unroll
    for (int i = 0; i < 4; i++) {
        int gr = m0 + ty*4 + i;
#pragma unroll
        for (int j = 0; j < 4; j++)
            Rs[(ty*4 + i)*260 + tx*4 + j] = c[i][j] + qin[gr*FF + tx*4 + j];
    }
    __syncthreads();

    int warp = tid >> 5, lane = tid & 31;
#pragma unroll
    for (int rr = warp*2; rr < warp*2 + 2; rr++) {
        float vals[8];
        float sum = 0.f, sq = 0.f;
#pragma unroll
        for (int t = 0; t < 8; t++) {
            float x = Rs[rr*260 + lane + t*32];
            vals[t] = x; sum += x; sq += x*x;
        }
#pragma unroll
        for (int off = 16; off; off >>= 1) {
            sum += __shfl_xor_sync(0xffffffffu, sum, off);
            sq  += __shfl_xor_sync(0xffffffffu, sq,  off);
        }
        float mu  = sum * (1.f/256.f);
        float var = sq * (1.f/256.f) - mu*mu;
        float rstd = rsqrtf(var + 1e-6f);
        int gr = m0 + rr;
#pragma unroll
        for (int t = 0; t < 8; t++) {
            int cI = lane + t*32;
            out[gr*FF + cI] = (vals[t] - mu) * rstd * lng[cI] + lnb[cI];
        }
    }
}

// ---------------------------------------------------------------------------
extern "C" void kernel_launch(void* const* d_in, const int* in_sizes, int n_in,
                              void* d_out, int out_size)
{
    const float* q    = (const float*)d_in[0];
    const float* v    = (const float*)d_in[2];   // d_in[1] (k) unused by model
    const float* w_qs = (const float*)d_in[3];
    const float* w_vs = (const float*)d_in[4];
    const float* w1   = (const float*)d_in[5];
    const float* b1   = (const float*)d_in[6];
    const float* w2   = (const float*)d_in[7];
    const float* b2   = (const float*)d_in[8];
    const float* fcw  = (const float*)d_in[9];
    const float* lng  = (const float*)d_in[10];
    const float* lnb  = (const float*)d_in[11];
    float* out = (float*)d_out;

    const int SM1 = (32*68*2 + 64*68*2) * 4;
    const int SM4 = (32*20 + 32*256) * 4;
    cudaFuncSetAttribute(k_proj,  cudaFuncAttributeMaxDynamicSharedMemorySize, SM1);
    cudaFuncSetAttribute(k_final, cudaFuncAttributeMaxDynamicSharedMemorySize, SM4);

    k_prep    <<<128, 256>>>(w2);
    k_proj    <<<dim3(BLL/64, HH, 2), 256, SM1>>>(q, v, w_qs, w_vs, w1, b1);
    k_attn_mma<<<dim3(8, HH, BB),     128>>>(b2);
    k_final   <<<BLL/16,              256, SM4>>>(q, fcw, lng, lnb, out);
}

// round 6
// speedup vs baseline: 2.3462x; 1.5944x over previous
#include <cuda_runtime.h>
#include <cuda_bf16.h>
#include <cstdint>

// MultiHeadDenseSynthesizer: B=64, L=500, F=256, H=4, dk=64
// Round 5: ALL GEMMs on mma.sync bf16 split hi/lo (3-term).
// Fix vs round 4: prep kernels must bind __device__ globals in DEVICE code
// (host-passed __device__ symbol addresses are host shadows -> silent zeros).

#define BB  64
#define LL  500
#define FF  256
#define HH  4
#define DKK 64
#define BLL (BB*LL)
#define BH  (BB*HH)
#define LPAD 512

// ---------------- device scratch (zero-initialized at load) ----------------
__device__ float g_ctx[BLL*FF];
__device__ uint4 g_wt_h4[BH*LL*DKK/8],   g_wt_l4[BH*LL*DKK/8];    // W  [bh][l][d]
__device__ uint4 g_vT_h4[BH*DKK*LPAD/8], g_vT_l4[BH*DKK*LPAD/8];  // Vt [bh][d][j]
__device__ uint4 g_w2T_h4[LPAD*DKK/8],   g_w2T_l4[LPAD*DKK/8];    // w2T [j][d]
__device__ uint4 g_wqsT4h[FF*FF/8], g_wqsT4l[FF*FF/8];            // [n][k]
__device__ uint4 g_wvsT4h[FF*FF/8], g_wvsT4l[FF*FF/8];
__device__ uint4 g_fcwT4h[FF*FF/8], g_fcwT4l[FF*FF/8];
__device__ uint4 g_w1T4h[DKK*DKK/8], g_w1T4l[DKK*DKK/8];

__device__ __forceinline__ uint32_t pack_bf2(__nv_bfloat16 a, __nv_bfloat16 b) {
    return (uint32_t)__bfloat16_as_ushort(a) | ((uint32_t)__bfloat16_as_ushort(b) << 16);
}
__device__ __forceinline__ void split2(float x, float y, uint32_t& h, uint32_t& l) {
    __nv_bfloat16 h0 = __float2bfloat16(x), h1 = __float2bfloat16(y);
    h = pack_bf2(h0, h1);
    l = pack_bf2(__float2bfloat16(x - __bfloat162float(h0)),
                 __float2bfloat16(y - __bfloat162float(h1)));
}
__device__ __forceinline__ void mma16816(float c[4], const uint32_t a[4], const uint32_t b[2]) {
    asm volatile(
        "mma.sync.aligned.m16n8k16.row.col.f32.bf16.bf16.f32 "
        "{%0,%1,%2,%3}, {%4,%5,%6,%7}, {%8,%9}, {%0,%1,%2,%3};"
        : "+f"(c[0]), "+f"(c[1]), "+f"(c[2]), "+f"(c[3])
        : "r"(a[0]), "r"(a[1]), "r"(a[2]), "r"(a[3]), "r"(b[0]), "r"(b[1]));
}

// ---------------------------------------------------------------------------
// k_prep_w2: w2 [64,500] -> w2T hi/lo [512,64] bf16 (zero rows 500..511)
// ---------------------------------------------------------------------------
__global__ void k_prep_w2(const float* __restrict__ w2)
{
    __nv_bfloat16* w2h = (__nv_bfloat16*)g_w2T_h4;
    __nv_bfloat16* w2l = (__nv_bfloat16*)g_w2T_l4;
    int idx = blockIdx.x * 256 + threadIdx.x;
    int j = idx >> 6, d = idx & 63;
    float v = (j < LL) ? w2[d*LL + j] : 0.f;
    __nv_bfloat16 h = __float2bfloat16(v);
    w2h[j*DKK + d] = h;
    w2l[j*DKK + d] = __float2bfloat16(v - __bfloat162float(h));
}

// ---------------------------------------------------------------------------
// k_prep_t: src [k][n] -> dst hi/lo [n][k] bf16 (transpose + split).
// Destination selected in DEVICE code (which: 0=wqs 1=wvs 2=fcw 3=w1).
// ---------------------------------------------------------------------------
__global__ void k_prep_t(const float* __restrict__ src, int which,
                         int kShift, int nDim, int total)
{
    __nv_bfloat16* dh;
    __nv_bfloat16* dl;
    switch (which) {
        case 0:  dh = (__nv_bfloat16*)g_wqsT4h; dl = (__nv_bfloat16*)g_wqsT4l; break;
        case 1:  dh = (__nv_bfloat16*)g_wvsT4h; dl = (__nv_bfloat16*)g_wvsT4l; break;
        case 2:  dh = (__nv_bfloat16*)g_fcwT4h; dl = (__nv_bfloat16*)g_fcwT4l; break;
        default: dh = (__nv_bfloat16*)g_w1T4h;  dl = (__nv_bfloat16*)g_w1T4l;  break;
    }
    int idx = blockIdx.x * 256 + threadIdx.x;
    if (idx >= total) return;
    int n = idx >> kShift, k = idx & ((1 << kShift) - 1);
    float v = src[k*nDim + n];
    __nv_bfloat16 h = __float2bfloat16(v);
    dh[idx] = h;
    dl[idx] = __float2bfloat16(v - __bfloat162float(h));
}

// ---------------------------------------------------------------------------
// Kernel 1: projections via mma.sync. grid (250, 4, 2), 256 thr (8 warps m16).
// mode 0: qh = q @ wqsT^T (head slice), then weight = relu(qh @ w1T^T + b1)
//         via C-frag->A-frag hand-off. Store g_wt hi/lo.
// mode 1: vh = v @ wvsT^T, transpose via smem -> g_vT hi/lo.
// ---------------------------------------------------------------------------
#define PJ_WPITCH 528   // 256 bf16 = 512B + 16 pad
#define PJ_W1OFF  (2*64*PJ_WPITCH)          // 67584
#define PJ_B1OFF  (PJ_W1OFF + 2*64*144)     // 86016
#define PJ_SMEM   (PJ_B1OFF + 256)          // 86272

__global__ void __launch_bounds__(256)
k_proj_mma(const float* __restrict__ qin, const float* __restrict__ vin,
           const float* __restrict__ b1)
{
    extern __shared__ char smem[];
    char* sWh  = smem;
    char* sWl  = smem + 64*PJ_WPITCH;
    char* sW1h = smem + PJ_W1OFF;
    char* sW1l = sW1h + 64*144;
    float* b1s = (float*)(smem + PJ_B1OFF);
    float* vtr = (float*)smem;          // mode1 alias: [64][132] fp32 (33792 B)

    const int tid  = threadIdx.x;
    const int lane = tid & 31, wid = tid >> 5;
    const int g4 = lane >> 2, t4 = lane & 3;
    const int m0 = blockIdx.x * 128;
    const int h  = blockIdx.y;
    const int mode = blockIdx.z;
    const float* A = mode ? vin : qin;
    const uint4* WTh = mode ? g_wvsT4h : g_wqsT4h;
    const uint4* WTl = mode ? g_wvsT4l : g_wqsT4l;

    // stage weight slice rows n=h*64..h*64+63, full k=256
    for (int idx = tid; idx < 2048; idx += 256) {
        int row = idx >> 5, c16 = idx & 31;
        *(uint4*)(sWh + row*PJ_WPITCH + c16*16) = WTh[(h*64 + row)*32 + c16];
        *(uint4*)(sWl + row*PJ_WPITCH + c16*16) = WTl[(h*64 + row)*32 + c16];
    }
    if (!mode) {
        for (int idx = tid; idx < 512; idx += 256) {
            int row = idx >> 3, gq = idx & 7;
            *(uint4*)(sW1h + row*144 + gq*16) = g_w1T4h[row*8 + gq];
            *(uint4*)(sW1l + row*144 + gq*16) = g_w1T4l[row*8 + gq];
        }
        if (tid < 64) b1s[tid] = b1[tid];
    }
    __syncthreads();

    const int r0 = wid*16 + g4;
    const int gr0 = m0 + r0, gr1 = gr0 + 8;

    float sacc[8][4];
#pragma unroll
    for (int nt = 0; nt < 8; nt++)
#pragma unroll
        for (int e = 0; e < 4; e++) sacc[nt][e] = 0.f;

#pragma unroll 4
    for (int kt = 0; kt < 16; kt++) {
        int c0 = kt*16 + t4*2;
        uint32_t ah[4], al[4];
        float2 f;
        f = *(const float2*)(A + (size_t)gr0*FF + c0);     split2(f.x, f.y, ah[0], al[0]);
        f = *(const float2*)(A + (size_t)gr1*FF + c0);     split2(f.x, f.y, ah[1], al[1]);
        f = *(const float2*)(A + (size_t)gr0*FF + c0 + 8); split2(f.x, f.y, ah[2], al[2]);
        f = *(const float2*)(A + (size_t)gr1*FF + c0 + 8); split2(f.x, f.y, ah[3], al[3]);
#pragma unroll
        for (int nt = 0; nt < 8; nt++) {
            int off = (nt*8 + g4)*PJ_WPITCH + c0*2;
            uint32_t bh2[2], bl2[2];
            bh2[0] = *(const uint32_t*)(sWh + off);
            bh2[1] = *(const uint32_t*)(sWh + off + 16);
            bl2[0] = *(const uint32_t*)(sWl + off);
            bl2[1] = *(const uint32_t*)(sWl + off + 16);
            mma16816(sacc[nt], ah, bh2);
            mma16816(sacc[nt], ah, bl2);
            mma16816(sacc[nt], al, bh2);
        }
    }

    if (mode) {
        // ---- transpose vh via smem -> g_vT [bh][d][j] hi/lo
        __syncthreads();
#pragma unroll
        for (int nt = 0; nt < 8; nt++) {
            int d0 = nt*8 + t4*2;
            vtr[d0*132 + r0]         = sacc[nt][0];
            vtr[(d0+1)*132 + r0]     = sacc[nt][1];
            vtr[d0*132 + r0 + 8]     = sacc[nt][2];
            vtr[(d0+1)*132 + r0 + 8] = sacc[nt][3];
        }
        __syncthreads();
        __nv_bfloat16* vTh = (__nv_bfloat16*)g_vT_h4;
        __nv_bfloat16* vTl = (__nv_bfloat16*)g_vT_l4;
        for (int idx = tid; idx < 4096; idx += 256) {
            int d = idx >> 6, jp = idx & 63;
            int gj = m0 + 2*jp;
            int b = gj / LL, p = gj - b*LL;   // pairs never cross batch (500 even)
            uint32_t hU, lU;
            split2(vtr[d*132 + 2*jp], vtr[d*132 + 2*jp + 1], hU, lU);
            size_t a = ((size_t)((b*HH + h)*DKK + d))*LPAD + p;
            *(uint32_t*)(vTh + a) = hU;
            *(uint32_t*)(vTl + a) = lU;
        }
        return;
    }

    // ---- hand-off: qh C-frags -> A-frags (hi/lo)
    uint32_t ph[4][4], pl[4][4];
#pragma unroll
    for (int nt = 0; nt < 8; nt++) {
        int kt = nt >> 1, i0 = (nt & 1) * 2;
        split2(sacc[nt][0], sacc[nt][1], ph[kt][i0],     pl[kt][i0]);
        split2(sacc[nt][2], sacc[nt][3], ph[kt][i0 + 1], pl[kt][i0 + 1]);
    }

    float s2[8][4];
#pragma unroll
    for (int nt = 0; nt < 8; nt++) {
        int col = nt*8 + t4*2;
        s2[nt][0] = s2[nt][2] = b1s[col];
        s2[nt][1] = s2[nt][3] = b1s[col + 1];
    }
#pragma unroll
    for (int kt = 0; kt < 4; kt++) {
#pragma unroll
        for (int nt = 0; nt < 8; nt++) {
            int off = (nt*8 + g4)*144 + (kt*16 + t4*2)*2;
            uint32_t bh2[2], bl2[2];
            bh2[0] = *(const uint32_t*)(sW1h + off);
            bh2[1] = *(const uint32_t*)(sW1h + off + 16);
            bl2[0] = *(const uint32_t*)(sW1l + off);
            bl2[1] = *(const uint32_t*)(sW1l + off + 16);
            mma16816(s2[nt], ph[kt], bh2);
            mma16816(s2[nt], ph[kt], bl2);
            mma16816(s2[nt], pl[kt], bh2);
        }
    }

    // relu + split + store g_wt
    __nv_bfloat16* wth = (__nv_bfloat16*)g_wt_h4;
    __nv_bfloat16* wtl = (__nv_bfloat16*)g_wt_l4;
    int b0_ = gr0 / LL, l0_ = gr0 - b0_*LL;
    int b1_ = gr1 / LL, l1_ = gr1 - b1_*LL;
    size_t base0 = ((size_t)((b0_*HH + h)*LL + l0_))*DKK;
    size_t base1 = ((size_t)((b1_*HH + h)*LL + l1_))*DKK;
#pragma unroll
    for (int nt = 0; nt < 8; nt++) {
        int d = nt*8 + t4*2;
        uint32_t hU, lU;
        split2(fmaxf(s2[nt][0], 0.f), fmaxf(s2[nt][1], 0.f), hU, lU);
        *(uint32_t*)(wth + base0 + d) = hU;
        *(uint32_t*)(wtl + base0 + d) = lU;
        split2(fmaxf(s2[nt][2], 0.f), fmaxf(s2[nt][3], 0.f), hU, lU);
        *(uint32_t*)(wth + base1 + d) = hU;
        *(uint32_t*)(wtl + base1 + d) = lU;
    }
}

// ---------------------------------------------------------------------------
// Kernel 2: mma.sync attention (validated round 3). grid (8, H, B), 128 thr.
// ---------------------------------------------------------------------------
#define SPITCH 144

__global__ void __launch_bounds__(128)
k_attn_mma(const float* __restrict__ b2)
{
    __shared__ float b2s[64];
    __shared__ __align__(16) char sW2h[64*SPITCH];
    __shared__ __align__(16) char sW2l[64*SPITCH];
    __shared__ __align__(16) char sVh [64*SPITCH];
    __shared__ __align__(16) char sVl [64*SPITCH];

    const int tid  = threadIdx.x;
    const int lane = tid & 31, wid = tid >> 5;
    const int g4 = lane >> 2, t4 = lane & 3;
    const int l0 = blockIdx.x * 64;
    const int h  = blockIdx.y, b = blockIdx.z;
    const int bh = b*HH + h;
    const int r0 = l0 + wid*16 + g4;

    const __nv_bfloat16* wth = (const __nv_bfloat16*)g_wt_h4;
    const __nv_bfloat16* wtl = (const __nv_bfloat16*)g_wt_l4;

    uint32_t aWh[4][4], aWl[4][4];
    {
        const bool v0 = (r0 < LL), v1 = (r0 + 8 < LL);
        size_t base0 = (size_t)(bh*LL + r0)*DKK;
        size_t base1 = (size_t)(bh*LL + r0 + 8)*DKK;
#pragma unroll
        for (int kt = 0; kt < 4; kt++) {
            int c0 = kt*16 + t4*2, c8 = c0 + 8;
            aWh[kt][0] = v0 ? *(const uint32_t*)(wth + base0 + c0) : 0u;
            aWh[kt][1] = v1 ? *(const uint32_t*)(wth + base1 + c0) : 0u;
            aWh[kt][2] = v0 ? *(const uint32_t*)(wth + base0 + c8) : 0u;
            aWh[kt][3] = v1 ? *(const uint32_t*)(wth + base1 + c8) : 0u;
            aWl[kt][0] = v0 ? *(const uint32_t*)(wtl + base0 + c0) : 0u;
            aWl[kt][1] = v1 ? *(const uint32_t*)(wtl + base1 + c0) : 0u;
            aWl[kt][2] = v0 ? *(const uint32_t*)(wtl + base0 + c8) : 0u;
            aWl[kt][3] = v1 ? *(const uint32_t*)(wtl + base1 + c8) : 0u;
        }
    }

    float oacc[8][4];
#pragma unroll
    for (int nt = 0; nt < 8; nt++)
#pragma unroll
        for (int e = 0; e < 4; e++) oacc[nt][e] = 0.f;
    float dp0 = 0.f, dp1 = 0.f;

    for (int c = 0; c < 8; c++) {
        const int j0 = c * 64;
        __syncthreads();
#pragma unroll
        for (int it = 0; it < 4; it++) {
            int idx = tid + it*128;
            int row = idx >> 3, gq = idx & 7;
            *(uint4*)(sW2h + row*SPITCH + gq*16) = g_w2T_h4[(size_t)(j0 + row)*8 + gq];
            *(uint4*)(sW2l + row*SPITCH + gq*16) = g_w2T_l4[(size_t)(j0 + row)*8 + gq];
            size_t sv = (size_t)(bh*DKK + row)*(LPAD/8) + (j0 >> 3) + gq;
            *(uint4*)(sVh + row*SPITCH + gq*16) = g_vT_h4[sv];
            *(uint4*)(sVl + row*SPITCH + gq*16) = g_vT_l4[sv];
        }
        if (tid < 64) b2s[tid] = (j0 + tid < LL) ? b2[j0 + tid] : 0.f;
        __syncthreads();

        float sacc[8][4];
#pragma unroll
        for (int nt = 0; nt < 8; nt++)
#pragma unroll
            for (int e = 0; e < 4; e++) sacc[nt][e] = 0.f;

#pragma unroll
        for (int kt = 0; kt < 4; kt++) {
#pragma unroll
            for (int nt = 0; nt < 8; nt++) {
                int off = (nt*8 + g4)*SPITCH + (kt*16 + t4*2)*2;
                uint32_t bh2[2], bl2[2];
                bh2[0] = *(const uint32_t*)(sW2h + off);
                bh2[1] = *(const uint32_t*)(sW2h + off + 16);
                bl2[0] = *(const uint32_t*)(sW2l + off);
                bl2[1] = *(const uint32_t*)(sW2l + off + 16);
                mma16816(sacc[nt], aWh[kt], bh2);
                mma16816(sacc[nt], aWh[kt], bl2);
                mma16816(sacc[nt], aWl[kt], bh2);
            }
        }

        uint32_t phA[4][4], plA[4][4];
#pragma unroll
        for (int nt = 0; nt < 8; nt++) {
            int jl = nt*8 + t4*2;
            int jg = j0 + jl;
            float bb0 = b2s[jl], bb1 = b2s[jl + 1];
            float p0 = (jg     < LL) ? __expf(sacc[nt][0] + bb0) : 0.f;
            float p1 = (jg + 1 < LL) ? __expf(sacc[nt][1] + bb1) : 0.f;
            float p2 = (jg     < LL) ? __expf(sacc[nt][2] + bb0) : 0.f;
            float p3 = (jg + 1 < LL) ? __expf(sacc[nt][3] + bb1) : 0.f;
            dp0 += p0 + p1;
            dp1 += p2 + p3;
            int kt = nt >> 1, i0 = (nt & 1) * 2;
            split2(p0, p1, phA[kt][i0],     plA[kt][i0]);
            split2(p2, p3, phA[kt][i0 + 1], plA[kt][i0 + 1]);
        }

#pragma unroll
        for (int kt = 0; kt < 4; kt++) {
#pragma unroll
            for (int nt = 0; nt < 8; nt++) {
                int off = (nt*8 + g4)*SPITCH + (kt*16 + t4*2)*2;
                uint32_t bvh[2], bvl[2];
                bvh[0] = *(const uint32_t*)(sVh + off);
                bvh[1] = *(const uint32_t*)(sVh + off + 16);
                bvl[0] = *(const uint32_t*)(sVl + off);
                bvl[1] = *(const uint32_t*)(sVl + off + 16);
                mma16816(oacc[nt], phA[kt], bvh);
                mma16816(oacc[nt], phA[kt], bvl);
                mma16816(oacc[nt], plA[kt], bvh);
            }
        }
    }

    dp0 += __shfl_xor_sync(0xffffffffu, dp0, 1);
    dp0 += __shfl_xor_sync(0xffffffffu, dp0, 2);
    dp1 += __shfl_xor_sync(0xffffffffu, dp1, 1);
    dp1 += __shfl_xor_sync(0xffffffffu, dp1, 2);
    float inv0 = 1.f / dp0, inv1 = 1.f / dp1;

    if (r0 < LL) {
        float* dst = g_ctx + ((size_t)(b*LL + r0))*FF + h*DKK + t4*2;
#pragma unroll
        for (int nt = 0; nt < 8; nt++) {
            float2 v; v.x = oacc[nt][0]*inv0; v.y = oacc[nt][1]*inv0;
            *(float2*)(dst + nt*8) = v;
        }
    }
    if (r0 + 8 < LL) {
        float* dst = g_ctx + ((size_t)(b*LL + r0 + 8))*FF + h*DKK + t4*2;
#pragma unroll
        for (int nt = 0; nt < 8; nt++) {
            float2 v; v.x = oacc[nt][2]*inv1; v.y = oacc[nt][3]*inv1;
            *(float2*)(dst + nt*8) = v;
        }
    }
}

// ---------------------------------------------------------------------------
// Kernel 3: out = LN(ctx @ fcwT^T + q) via mma.sync. grid 250, 256 thr, M=128.
// ---------------------------------------------------------------------------
#define FN_SMEM (2*256*144)   // 73728

__global__ void __launch_bounds__(256)
k_final_mma(const float* __restrict__ qin, const float* __restrict__ lng,
            const float* __restrict__ lnb, float* __restrict__ out)
{
    extern __shared__ char smem[];
    char* sFh = smem;
    char* sFl = smem + 256*144;

    const int tid  = threadIdx.x;
    const int lane = tid & 31, wid = tid >> 5;
    const int g4 = lane >> 2, t4 = lane & 3;
    const int m0 = blockIdx.x * 128;
    const int r0 = wid*16 + g4;
    const int gr0 = m0 + r0, gr1 = gr0 + 8;

    float sacc[32][4];
#pragma unroll
    for (int nt = 0; nt < 32; nt++)
#pragma unroll
        for (int e = 0; e < 4; e++) sacc[nt][e] = 0.f;

    for (int kc = 0; kc < 4; kc++) {
        __syncthreads();
        for (int idx = tid; idx < 2048; idx += 256) {
            int row = idx >> 3, gq = idx & 7;
            *(uint4*)(sFh + row*144 + gq*16) = g_fcwT4h[row*32 + kc*8 + gq];
            *(uint4*)(sFl + row*144 + gq*16) = g_fcwT4l[row*32 + kc*8 + gq];
        }
        __syncthreads();

#pragma unroll
        for (int kt = 0; kt < 4; kt++) {
            int cg = kc*64 + kt*16 + t4*2;
            uint32_t ah[4], al[4];
            float2 f;
            f = *(const float2*)(g_ctx + (size_t)gr0*FF + cg);     split2(f.x, f.y, ah[0], al[0]);
            f = *(const float2*)(g_ctx + (size_t)gr1*FF + cg);     split2(f.x, f.y, ah[1], al[1]);
            f = *(const float2*)(g_ctx + (size_t)gr0*FF + cg + 8); split2(f.x, f.y, ah[2], al[2]);
            f = *(const float2*)(g_ctx + (size_t)gr1*FF + cg + 8); split2(f.x, f.y, ah[3], al[3]);
            int koff = (kt*16 + t4*2)*2;
#pragma unroll
            for (int nt = 0; nt < 32; nt++) {
                int off = (nt*8 + g4)*144 + koff;
                uint32_t bh2[2], bl2[2];
                bh2[0] = *(const uint32_t*)(sFh + off);
                bh2[1] = *(const uint32_t*)(sFh + off + 16);
                bl2[0] = *(const uint32_t*)(sFl + off);
                bl2[1] = *(const uint32_t*)(sFl + off + 16);
                mma16816(sacc[nt], ah, bh2);
                mma16816(sacc[nt], ah, bl2);
                mma16816(sacc[nt], al, bh2);
            }
        }
    }

    // residual + LN stats
    float sum0 = 0.f, sq0 = 0.f, sum1 = 0.f, sq1 = 0.f;
#pragma unroll
    for (int nt = 0; nt < 32; nt++) {
        int col = nt*8 + t4*2;
        float2 q0 = *(const float2*)(qin + (size_t)gr0*FF + col);
        float2 q1 = *(const float2*)(qin + (size_t)gr1*FF + col);
        sacc[nt][0] += q0.x; sacc[nt][1] += q0.y;
        sacc[nt][2] += q1.x; sacc[nt][3] += q1.y;
        sum0 += sacc[nt][0] + sacc[nt][1];
        sq0  += sacc[nt][0]*sacc[nt][0] + sacc[nt][1]*sacc[nt][1];
        sum1 += sacc[nt][2] + sacc[nt][3];
        sq1  += sacc[nt][2]*sacc[nt][2] + sacc[nt][3]*sacc[nt][3];
    }
    sum0 += __shfl_xor_sync(0xffffffffu, sum0, 1);
    sum0 += __shfl_xor_sync(0xffffffffu, sum0, 2);
    sq0  += __shfl_xor_sync(0xffffffffu, sq0, 1);
    sq0  += __shfl_xor_sync(0xffffffffu, sq0, 2);
    sum1 += __shfl_xor_sync(0xffffffffu, sum1, 1);
    sum1 += __shfl_xor_sync(0xffffffffu, sum1, 2);
    sq1  += __shfl_xor_sync(0xffffffffu, sq1, 1);
    sq1  += __shfl_xor_sync(0xffffffffu, sq1, 2);

    float mu0 = sum0 * (1.f/256.f);
    float mu1 = sum1 * (1.f/256.f);
    float rstd0 = rsqrtf(sq0 * (1.f/256.f) - mu0*mu0 + 1e-6f);
    float rstd1 = rsqrtf(sq1 * (1.f/256.f) - mu1*mu1 + 1e-6f);

#pragma unroll
    for (int nt = 0; nt < 32; nt++) {
        int col = nt*8 + t4*2;
        float2 g = *(const float2*)(lng + col);
        float2 bt = *(const float2*)(lnb + col);
        float2 o0, o1;
        o0.x = (sacc[nt][0] - mu0)*rstd0*g.x + bt.x;
        o0.y = (sacc[nt][1] - mu0)*rstd0*g.y + bt.y;
        o1.x = (sacc[nt][2] - mu1)*rstd1*g.x + bt.x;
        o1.y = (sacc[nt][3] - mu1)*rstd1*g.y + bt.y;
        *(float2*)(out + (size_t)gr0*FF + col) = o0;
        *(float2*)(out + (size_t)gr1*FF + col) = o1;
    }
}

// ---------------------------------------------------------------------------
extern "C" void kernel_launch(void* const* d_in, const int* in_sizes, int n_in,
                              void* d_out, int out_size)
{
    const float* q    = (const float*)d_in[0];
    const float* v    = (const float*)d_in[2];   // d_in[1] (k) unused by model
    const float* w_qs = (const float*)d_in[3];
    const float* w_vs = (const float*)d_in[4];
    const float* w1   = (const float*)d_in[5];
    const float* b1   = (const float*)d_in[6];
    const float* w2   = (const float*)d_in[7];
    const float* b2   = (const float*)d_in[8];
    const float* fcw  = (const float*)d_in[9];
    const float* lng  = (const float*)d_in[10];
    const float* lnb  = (const float*)d_in[11];
    float* out = (float*)d_out;

    cudaFuncSetAttribute(k_proj_mma,  cudaFuncAttributeMaxDynamicSharedMemorySize, PJ_SMEM);
    cudaFuncSetAttribute(k_final_mma, cudaFuncAttributeMaxDynamicSharedMemorySize, FN_SMEM);

    k_prep_w2<<<128, 256>>>(w2);
    k_prep_t<<<256, 256>>>(w_qs, 0, 8, FF, FF*FF);
    k_prep_t<<<256, 256>>>(w_vs, 1, 8, FF, FF*FF);
    k_prep_t<<<256, 256>>>(fcw,  2, 8, FF, FF*FF);
    k_prep_t<<<16,  256>>>(w1,   3, 6, DKK, DKK*DKK);

    k_proj_mma <<<dim3(250, HH, 2), 256, PJ_SMEM>>>(q, v, b1);
    k_attn_mma <<<dim3(8, HH, BB),  128>>>(b2);
    k_final_mma<<<250,              256, FN_SMEM>>>(q, lng, lnb, out);
}

// round 10
// speedup vs baseline: 3.1610x; 1.3473x over previous
#include <cuda_runtime.h>
#include <cuda_bf16.h>
#include <cstdint>

// MultiHeadDenseSynthesizer: B=64, L=500, F=256, H=4, dk=64
// Round 6: 2-term split MMA (a_hi*b_hi + a_hi*b_lo) everywhere; merged prep.

#define BB  64
#define LL  500
#define FF  256
#define HH  4
#define DKK 64
#define BLL (BB*LL)
#define BH  (BB*HH)
#define LPAD 512

// ---------------- device scratch (zero-initialized at load) ----------------
__device__ float g_ctx[BLL*FF];
__device__ uint4 g_wt_h4[BH*LL*DKK/8];                            // W  [bh][l][d] (hi only; A-side)
__device__ uint4 g_vT_h4[BH*DKK*LPAD/8], g_vT_l4[BH*DKK*LPAD/8];  // Vt [bh][d][j] (B-side: hi/lo)
__device__ uint4 g_w2T_h4[LPAD*DKK/8],   g_w2T_l4[LPAD*DKK/8];    // w2T [j][d]
__device__ uint4 g_wqsT4h[FF*FF/8], g_wqsT4l[FF*FF/8];            // [n][k]
__device__ uint4 g_wvsT4h[FF*FF/8], g_wvsT4l[FF*FF/8];
__device__ uint4 g_fcwT4h[FF*FF/8], g_fcwT4l[FF*FF/8];
__device__ uint4 g_w1T4h[DKK*DKK/8], g_w1T4l[DKK*DKK/8];

__device__ __forceinline__ uint32_t pack_bf2(__nv_bfloat16 a, __nv_bfloat16 b) {
    return (uint32_t)__bfloat16_as_ushort(a) | ((uint32_t)__bfloat16_as_ushort(b) << 16);
}
__device__ __forceinline__ uint32_t pack_hi2(float x, float y) {
    __nv_bfloat162 t = __float22bfloat162_rn(make_float2(x, y));
    return *(uint32_t*)&t;
}
__device__ __forceinline__ void split2(float x, float y, uint32_t& h, uint32_t& l) {
    __nv_bfloat16 h0 = __float2bfloat16(x), h1 = __float2bfloat16(y);
    h = pack_bf2(h0, h1);
    l = pack_bf2(__float2bfloat16(x - __bfloat162float(h0)),
                 __float2bfloat16(y - __bfloat162float(h1)));
}
__device__ __forceinline__ void mma16816(float c[4], const uint32_t a[4], const uint32_t b[2]) {
    asm volatile(
        "mma.sync.aligned.m16n8k16.row.col.f32.bf16.bf16.f32 "
        "{%0,%1,%2,%3}, {%4,%5,%6,%7}, {%8,%9}, {%0,%1,%2,%3};"
        : "+f"(c[0]), "+f"(c[1]), "+f"(c[2]), "+f"(c[3])
        : "r"(a[0]), "r"(a[1]), "r"(a[2]), "r"(a[3]), "r"(b[0]), "r"(b[1]));
}

// ---------------------------------------------------------------------------
// k_prep_all: one kernel for all weight transposes + hi/lo splits.
// blocks [0,128): w2T, [128,384): wqsT, [384,640): wvsT, [640,896): fcwT,
// [896,912): w1T.   (912 blocks x 256 threads)
// ---------------------------------------------------------------------------
__global__ void k_prep_all(const float* __restrict__ w2, const float* __restrict__ wqs,
                           const float* __restrict__ wvs, const float* __restrict__ fcw,
                           const float* __restrict__ w1)
{
    int bx = blockIdx.x, tid = threadIdx.x;
    float v; __nv_bfloat16* dh; __nv_bfloat16* dl; int idx;
    if (bx < 128) {
        idx = bx*256 + tid;                       // j*64 + d
        int j = idx >> 6, d = idx & 63;
        v = (j < LL) ? w2[d*LL + j] : 0.f;
        dh = (__nv_bfloat16*)g_w2T_h4; dl = (__nv_bfloat16*)g_w2T_l4;
    } else if (bx < 384) {
        idx = (bx - 128)*256 + tid;               // n*256 + k
        int n = idx >> 8, k = idx & 255;
        v = wqs[k*FF + n];
        dh = (__nv_bfloat16*)g_wqsT4h; dl = (__nv_bfloat16*)g_wqsT4l;
    } else if (bx < 640) {
        idx = (bx - 384)*256 + tid;
        int n = idx >> 8, k = idx & 255;
        v = wvs[k*FF + n];
        dh = (__nv_bfloat16*)g_wvsT4h; dl = (__nv_bfloat16*)g_wvsT4l;
    } else if (bx < 896) {
        idx = (bx - 640)*256 + tid;
        int n = idx >> 8, k = idx & 255;
        v = fcw[k*FF + n];
        dh = (__nv_bfloat16*)g_fcwT4h; dl = (__nv_bfloat16*)g_fcwT4l;
    } else {
        idx = (bx - 896)*256 + tid;               // n*64 + k
        int n = idx >> 6, k = idx & 63;
        v = w1[k*DKK + n];
        dh = (__nv_bfloat16*)g_w1T4h; dl = (__nv_bfloat16*)g_w1T4l;
    }
    __nv_bfloat16 h = __float2bfloat16(v);
    dh[idx] = h;
    dl[idx] = __float2bfloat16(v - __bfloat162float(h));
}

// ---------------------------------------------------------------------------
// Kernel 1: projections via mma.sync (2-term). grid (250, 4, 2), 256 thr.
// ---------------------------------------------------------------------------
#define PJ_WPITCH 528
#define PJ_W1OFF  (2*64*PJ_WPITCH)          // 67584
#define PJ_B1OFF  (PJ_W1OFF + 2*64*144)     // 86016
#define PJ_SMEM   (PJ_B1OFF + 256)          // 86272

__global__ void __launch_bounds__(256)
k_proj_mma(const float* __restrict__ qin, const float* __restrict__ vin,
           const float* __restrict__ b1)
{
    extern __shared__ char smem[];
    char* sWh  = smem;
    char* sWl  = smem + 64*PJ_WPITCH;
    char* sW1h = smem + PJ_W1OFF;
    char* sW1l = sW1h + 64*144;
    float* b1s = (float*)(smem + PJ_B1OFF);
    float* vtr = (float*)smem;          // mode1 alias: [64][132] fp32

    const int tid  = threadIdx.x;
    const int lane = tid & 31, wid = tid >> 5;
    const int g4 = lane >> 2, t4 = lane & 3;
    const int m0 = blockIdx.x * 128;
    const int h  = blockIdx.y;
    const int mode = blockIdx.z;
    const float* A = mode ? vin : qin;
    const uint4* WTh = mode ? g_wvsT4h : g_wqsT4h;
    const uint4* WTl = mode ? g_wvsT4l : g_wqsT4l;

    for (int idx = tid; idx < 2048; idx += 256) {
        int row = idx >> 5, c16 = idx & 31;
        *(uint4*)(sWh + row*PJ_WPITCH + c16*16) = WTh[(h*64 + row)*32 + c16];
        *(uint4*)(sWl + row*PJ_WPITCH + c16*16) = WTl[(h*64 + row)*32 + c16];
    }
    if (!mode) {
        for (int idx = tid; idx < 512; idx += 256) {
            int row = idx >> 3, gq = idx & 7;
            *(uint4*)(sW1h + row*144 + gq*16) = g_w1T4h[row*8 + gq];
            *(uint4*)(sW1l + row*144 + gq*16) = g_w1T4l[row*8 + gq];
        }
        if (tid < 64) b1s[tid] = b1[tid];
    }
    __syncthreads();

    const int r0 = wid*16 + g4;
    const int gr0 = m0 + r0, gr1 = gr0 + 8;

    float sacc[8][4];
#pragma unroll
    for (int nt = 0; nt < 8; nt++)
#pragma unroll
        for (int e = 0; e < 4; e++) sacc[nt][e] = 0.f;

#pragma unroll 4
    for (int kt = 0; kt < 16; kt++) {
        int c0 = kt*16 + t4*2;
        uint32_t ah[4];
        float2 f;
        f = *(const float2*)(A + (size_t)gr0*FF + c0);     ah[0] = pack_hi2(f.x, f.y);
        f = *(const float2*)(A + (size_t)gr1*FF + c0);     ah[1] = pack_hi2(f.x, f.y);
        f = *(const float2*)(A + (size_t)gr0*FF + c0 + 8); ah[2] = pack_hi2(f.x, f.y);
        f = *(const float2*)(A + (size_t)gr1*FF + c0 + 8); ah[3] = pack_hi2(f.x, f.y);
#pragma unroll
        for (int nt = 0; nt < 8; nt++) {
            int off = (nt*8 + g4)*PJ_WPITCH + c0*2;
            uint32_t bh2[2], bl2[2];
            bh2[0] = *(const uint32_t*)(sWh + off);
            bh2[1] = *(const uint32_t*)(sWh + off + 16);
            bl2[0] = *(const uint32_t*)(sWl + off);
            bl2[1] = *(const uint32_t*)(sWl + off + 16);
            mma16816(sacc[nt], ah, bh2);
            mma16816(sacc[nt], ah, bl2);
        }
    }

    if (mode) {
        // ---- transpose vh via smem -> g_vT [bh][d][j] hi/lo (B-side: keep lo)
        __syncthreads();
#pragma unroll
        for (int nt = 0; nt < 8; nt++) {
            int d0 = nt*8 + t4*2;
            vtr[d0*132 + r0]         = sacc[nt][0];
            vtr[(d0+1)*132 + r0]     = sacc[nt][1];
            vtr[d0*132 + r0 + 8]     = sacc[nt][2];
            vtr[(d0+1)*132 + r0 + 8] = sacc[nt][3];
        }
        __syncthreads();
        __nv_bfloat16* vTh = (__nv_bfloat16*)g_vT_h4;
        __nv_bfloat16* vTl = (__nv_bfloat16*)g_vT_l4;
        for (int idx = tid; idx < 4096; idx += 256) {
            int d = idx >> 6, jp = idx & 63;
            int gj = m0 + 2*jp;
            int b = gj / LL, p = gj - b*LL;   // pairs never cross batch (500 even)
            uint32_t hU, lU;
            split2(vtr[d*132 + 2*jp], vtr[d*132 + 2*jp + 1], hU, lU);
            size_t a = ((size_t)((b*HH + h)*DKK + d))*LPAD + p;
            *(uint32_t*)(vTh + a) = hU;
            *(uint32_t*)(vTl + a) = lU;
        }
        return;
    }

    // ---- hand-off: qh C-frags -> A-frags (hi only)
    uint32_t ph[4][4];
#pragma unroll
    for (int nt = 0; nt < 8; nt++) {
        int kt = nt >> 1, i0 = (nt & 1) * 2;
        ph[kt][i0]     = pack_hi2(sacc[nt][0], sacc[nt][1]);
        ph[kt][i0 + 1] = pack_hi2(sacc[nt][2], sacc[nt][3]);
    }

    float s2[8][4];
#pragma unroll
    for (int nt = 0; nt < 8; nt++) {
        int col = nt*8 + t4*2;
        s2[nt][0] = s2[nt][2] = b1s[col];
        s2[nt][1] = s2[nt][3] = b1s[col + 1];
    }
#pragma unroll
    for (int kt = 0; kt < 4; kt++) {
#pragma unroll
        for (int nt = 0; nt < 8; nt++) {
            int off = (nt*8 + g4)*144 + (kt*16 + t4*2)*2;
            uint32_t bh2[2], bl2[2];
            bh2[0] = *(const uint32_t*)(sW1h + off);
            bh2[1] = *(const uint32_t*)(sW1h + off + 16);
            bl2[0] = *(const uint32_t*)(sW1l + off);
            bl2[1] = *(const uint32_t*)(sW1l + off + 16);
            mma16816(s2[nt], ph[kt], bh2);
            mma16816(s2[nt], ph[kt], bl2);
        }
    }

    // relu + store g_wt (hi only; A-side operand downstream)
    __nv_bfloat16* wth = (__nv_bfloat16*)g_wt_h4;
    int b0_ = gr0 / LL, l0_ = gr0 - b0_*LL;
    int b1_ = gr1 / LL, l1_ = gr1 - b1_*LL;
    size_t base0 = ((size_t)((b0_*HH + h)*LL + l0_))*DKK;
    size_t base1 = ((size_t)((b1_*HH + h)*LL + l1_))*DKK;
#pragma unroll
    for (int nt = 0; nt < 8; nt++) {
        int d = nt*8 + t4*2;
        *(uint32_t*)(wth + base0 + d) =
            pack_hi2(fmaxf(s2[nt][0], 0.f), fmaxf(s2[nt][1], 0.f));
        *(uint32_t*)(wth + base1 + d) =
            pack_hi2(fmaxf(s2[nt][2], 0.f), fmaxf(s2[nt][3], 0.f));
    }
}

// ---------------------------------------------------------------------------
// Kernel 2: mma.sync attention (2-term). grid (8, H, B), 128 thr.
// ---------------------------------------------------------------------------
#define SPITCH 144

__global__ void __launch_bounds__(128)
k_attn_mma(const float* __restrict__ b2)
{
    __shared__ float b2s[64];
    __shared__ __align__(16) char sW2h[64*SPITCH];
    __shared__ __align__(16) char sW2l[64*SPITCH];
    __shared__ __align__(16) char sVh [64*SPITCH];
    __shared__ __align__(16) char sVl [64*SPITCH];

    const int tid  = threadIdx.x;
    const int lane = tid & 31, wid = tid >> 5;
    const int g4 = lane >> 2, t4 = lane & 3;
    const int l0 = blockIdx.x * 64;
    const int h  = blockIdx.y, b = blockIdx.z;
    const int bh = b*HH + h;
    const int r0 = l0 + wid*16 + g4;

    const __nv_bfloat16* wth = (const __nv_bfloat16*)g_wt_h4;

    uint32_t aWh[4][4];
    {
        const bool v0 = (r0 < LL), v1 = (r0 + 8 < LL);
        size_t base0 = (size_t)(bh*LL + r0)*DKK;
        size_t base1 = (size_t)(bh*LL + r0 + 8)*DKK;
#pragma unroll
        for (int kt = 0; kt < 4; kt++) {
            int c0 = kt*16 + t4*2, c8 = c0 + 8;
            aWh[kt][0] = v0 ? *(const uint32_t*)(wth + base0 + c0) : 0u;
            aWh[kt][1] = v1 ? *(const uint32_t*)(wth + base1 + c0) : 0u;
            aWh[kt][2] = v0 ? *(const uint32_t*)(wth + base0 + c8) : 0u;
            aWh[kt][3] = v1 ? *(const uint32_t*)(wth + base1 + c8) : 0u;
        }
    }

    float oacc[8][4];
#pragma unroll
    for (int nt = 0; nt < 8; nt++)
#pragma unroll
        for (int e = 0; e < 4; e++) oacc[nt][e] = 0.f;
    float dp0 = 0.f, dp1 = 0.f;

    for (int c = 0; c < 8; c++) {
        const int j0 = c * 64;
        __syncthreads();
#pragma unroll
        for (int it = 0; it < 4; it++) {
            int idx = tid + it*128;
            int row = idx >> 3, gq = idx & 7;
            *(uint4*)(sW2h + row*SPITCH + gq*16) = g_w2T_h4[(size_t)(j0 + row)*8 + gq];
            *(uint4*)(sW2l + row*SPITCH + gq*16) = g_w2T_l4[(size_t)(j0 + row)*8 + gq];
            size_t sv = (size_t)(bh*DKK + row)*(LPAD/8) + (j0 >> 3) + gq;
            *(uint4*)(sVh + row*SPITCH + gq*16) = g_vT_h4[sv];
            *(uint4*)(sVl + row*SPITCH + gq*16) = g_vT_l4[sv];
        }
        if (tid < 64) b2s[tid] = (j0 + tid < LL) ? b2[j0 + tid] : 0.f;
        __syncthreads();

        float sacc[8][4];
#pragma unroll
        for (int nt = 0; nt < 8; nt++)
#pragma unroll
            for (int e = 0; e < 4; e++) sacc[nt][e] = 0.f;

#pragma unroll
        for (int kt = 0; kt < 4; kt++) {
#pragma unroll
            for (int nt = 0; nt < 8; nt++) {
                int off = (nt*8 + g4)*SPITCH + (kt*16 + t4*2)*2;
                uint32_t bh2[2], bl2[2];
                bh2[0] = *(const uint32_t*)(sW2h + off);
                bh2[1] = *(const uint32_t*)(sW2h + off + 16);
                bl2[0] = *(const uint32_t*)(sW2l + off);
                bl2[1] = *(const uint32_t*)(sW2l + off + 16);
                mma16816(sacc[nt], aWh[kt], bh2);
                mma16816(sacc[nt], aWh[kt], bl2);
            }
        }

        uint32_t phA[4][4];
#pragma unroll
        for (int nt = 0; nt < 8; nt++) {
            int jl = nt*8 + t4*2;
            int jg = j0 + jl;
            float bb0 = b2s[jl], bb1 = b2s[jl + 1];
            float p0 = (jg     < LL) ? __expf(sacc[nt][0] + bb0) : 0.f;
            float p1 = (jg + 1 < LL) ? __expf(sacc[nt][1] + bb1) : 0.f;
            float p2 = (jg     < LL) ? __expf(sacc[nt][2] + bb0) : 0.f;
            float p3 = (jg + 1 < LL) ? __expf(sacc[nt][3] + bb1) : 0.f;
            dp0 += p0 + p1;
            dp1 += p2 + p3;
            int kt = nt >> 1, i0 = (nt & 1) * 2;
            phA[kt][i0]     = pack_hi2(p0, p1);
            phA[kt][i0 + 1] = pack_hi2(p2, p3);
        }

#pragma unroll
        for (int kt = 0; kt < 4; kt++) {
#pragma unroll
            for (int nt = 0; nt < 8; nt++) {
                int off = (nt*8 + g4)*SPITCH + (kt*16 + t4*2)*2;
                uint32_t bvh[2], bvl[2];
                bvh[0] = *(const uint32_t*)(sVh + off);
                bvh[1] = *(const uint32_t*)(sVh + off + 16);
                bvl[0] = *(const uint32_t*)(sVl + off);
                bvl[1] = *(const uint32_t*)(sVl + off + 16);
                mma16816(oacc[nt], phA[kt], bvh);
                mma16816(oacc[nt], phA[kt], bvl);
            }
        }
    }

    dp0 += __shfl_xor_sync(0xffffffffu, dp0, 1);
    dp0 += __shfl_xor_sync(0xffffffffu, dp0, 2);
    dp1 += __shfl_xor_sync(0xffffffffu, dp1, 1);
    dp1 += __shfl_xor_sync(0xffffffffu, dp1, 2);
    float inv0 = 1.f / dp0, inv1 = 1.f / dp1;

    if (r0 < LL) {
        float* dst = g_ctx + ((size_t)(b*LL + r0))*FF + h*DKK + t4*2;
#pragma unroll
        for (int nt = 0; nt < 8; nt++) {
            float2 v; v.x = oacc[nt][0]*inv0; v.y = oacc[nt][1]*inv0;
            *(float2*)(dst + nt*8) = v;
        }
    }
    if (r0 + 8 < LL) {
        float* dst = g_ctx + ((size_t)(b*LL + r0 + 8))*FF + h*DKK + t4*2;
#pragma unroll
        for (int nt = 0; nt < 8; nt++) {
            float2 v; v.x = oacc[nt][2]*inv1; v.y = oacc[nt][3]*inv1;
            *(float2*)(dst + nt*8) = v;
        }
    }
}

// ---------------------------------------------------------------------------
// Kernel 3: out = LN(ctx @ fcwT^T + q) via mma.sync (2-term). grid 250, 256 thr.
// ---------------------------------------------------------------------------
#define FN_SMEM (2*256*144)   // 73728

__global__ void __launch_bounds__(256)
k_final_mma(const float* __restrict__ qin, const float* __restrict__ lng,
            const float* __restrict__ lnb, float* __restrict__ out)
{
    extern __shared__ char smem[];
    char* sFh = smem;
    char* sFl = smem + 256*144;

    const int tid  = threadIdx.x;
    const int lane = tid & 31, wid = tid >> 5;
    const int g4 = lane >> 2, t4 = lane & 3;
    const int m0 = blockIdx.x * 128;
    const int r0 = wid*16 + g4;
    const int gr0 = m0 + r0, gr1 = gr0 + 8;

    float sacc[32][4];
#pragma unroll
    for (int nt = 0; nt < 32; nt++)
#pragma unroll
        for (int e = 0; e < 4; e++) sacc[nt][e] = 0.f;

    for (int kc = 0; kc < 4; kc++) {
        __syncthreads();
        for (int idx = tid; idx < 2048; idx += 256) {
            int row = idx >> 3, gq = idx & 7;
            *(uint4*)(sFh + row*144 + gq*16) = g_fcwT4h[row*32 + kc*8 + gq];
            *(uint4*)(sFl + row*144 + gq*16) = g_fcwT4l[row*32 + kc*8 + gq];
        }
        __syncthreads();

#pragma unroll
        for (int kt = 0; kt < 4; kt++) {
            int cg = kc*64 + kt*16 + t4*2;
            uint32_t ah[4];
            float2 f;
            f = *(const float2*)(g_ctx + (size_t)gr0*FF + cg);     ah[0] = pack_hi2(f.x, f.y);
            f = *(const float2*)(g_ctx + (size_t)gr1*FF + cg);     ah[1] = pack_hi2(f.x, f.y);
            f = *(const float2*)(g_ctx + (size_t)gr0*FF + cg + 8); ah[2] = pack_hi2(f.x, f.y);
            f = *(const float2*)(g_ctx + (size_t)gr1*FF + cg + 8); ah[3] = pack_hi2(f.x, f.y);
            int koff = (kt*16 + t4*2)*2;
#pragma unroll
            for (int nt = 0; nt < 32; nt++) {
                int off = (nt*8 + g4)*144 + koff;
                uint32_t bh2[2], bl2[2];
                bh2[0] = *(const uint32_t*)(sFh + off);
                bh2[1] = *(const uint32_t*)(sFh + off + 16);
                bl2[0] = *(const uint32_t*)(sFl + off);
                bl2[1] = *(const uint32_t*)(sFl + off + 16);
                mma16816(sacc[nt], ah, bh2);
                mma16816(sacc[nt], ah, bl2);
            }
        }
    }

    // residual + LN stats
    float sum0 = 0.f, sq0 = 0.f, sum1 = 0.f, sq1 = 0.f;
#pragma unroll
    for (int nt = 0; nt < 32; nt++) {
        int col = nt*8 + t4*2;
        float2 q0 = *(const float2*)(qin + (size_t)gr0*FF + col);
        float2 q1 = *(const float2*)(qin + (size_t)gr1*FF + col);
        sacc[nt][0] += q0.x; sacc[nt][1] += q0.y;
        sacc[nt][2] += q1.x; sacc[nt][3] += q1.y;
        sum0 += sacc[nt][0] + sacc[nt][1];
        sq0  += sacc[nt][0]*sacc[nt][0] + sacc[nt][1]*sacc[nt][1];
        sum1 += sacc[nt][2] + sacc[nt][3];
        sq1  += sacc[nt][2]*sacc[nt][2] + sacc[nt][3]*sacc[nt][3];
    }
    sum0 += __shfl_xor_sync(0xffffffffu, sum0, 1);
    sum0 += __shfl_xor_sync(0xffffffffu, sum0, 2);
    sq0  += __shfl_xor_sync(0xffffffffu, sq0, 1);
    sq0  += __shfl_xor_sync(0xffffffffu, sq0, 2);
    sum1 += __shfl_xor_sync(0xffffffffu, sum1, 1);
    sum1 += __shfl_xor_sync(0xffffffffu, sum1, 2);
    sq1  += __shfl_xor_sync(0xffffffffu, sq1, 1);
    sq1  += __shfl_xor_sync(0xffffffffu, sq1, 2);

    float mu0 = sum0 * (1.f/256.f);
    float mu1 = sum1 * (1.f/256.f);
    float rstd0 = rsqrtf(sq0 * (1.f/256.f) - mu0*mu0 + 1e-6f);
    float rstd1 = rsqrtf(sq1 * (1.f/256.f) - mu1*mu1 + 1e-6f);

#pragma unroll
    for (int nt = 0; nt < 32; nt++) {
        int col = nt*8 + t4*2;
        float2 g = *(const float2*)(lng + col);
        float2 bt = *(const float2*)(lnb + col);
        float2 o0, o1;
        o0.x = (sacc[nt][0] - mu0)*rstd0*g.x + bt.x;
        o0.y = (sacc[nt][1] - mu0)*rstd0*g.y + bt.y;
        o1.x = (sacc[nt][2] - mu1)*rstd1*g.x + bt.x;
        o1.y = (sacc[nt][3] - mu1)*rstd1*g.y + bt.y;
        *(float2*)(out + (size_t)gr0*FF + col) = o0;
        *(float2*)(out + (size_t)gr1*FF + col) = o1;
    }
}

// ---------------------------------------------------------------------------
extern "C" void kernel_launch(void* const* d_in, const int* in_sizes, int n_in,
                              void* d_out, int out_size)
{
    const float* q    = (const float*)d_in[0];
    const float* v    = (const float*)d_in[2];   // d_in[1] (k) unused by model
    const float* w_qs = (const float*)d_in[3];
    const float* w_vs = (const float*)d_in[4];
    const float* w1   = (const float*)d_in[5];
    const float* b1   = (const float*)d_in[6];
    const float* w2   = (const float*)d_in[7];
    const float* b2   = (const float*)d_in[8];
    const float* fcw  = (const float*)d_in[9];
    const float* lng  = (const float*)d_in[10];
    const float* lnb  = (const float*)d_in[11];
    float* out = (float*)d_out;

    cudaFuncSetAttribute(k_proj_mma,  cudaFuncAttributeMaxDynamicSharedMemorySize, PJ_SMEM);
    cudaFuncSetAttribute(k_final_mma, cudaFuncAttributeMaxDynamicSharedMemorySize, FN_SMEM);

    k_prep_all <<<912, 256>>>(w2, w_qs, w_vs, fcw, w1);
    k_proj_mma <<<dim3(250, HH, 2), 256, PJ_SMEM>>>(q, v, b1);
    k_attn_mma <<<dim3(8, HH, BB),  128>>>(b2);
    k_final_mma<<<250,              256, FN_SMEM>>>(q, lng, lnb, out);
}

// round 11
// speedup vs baseline: 4.3304x; 1.3700x over previous
#include <cuda_runtime.h>
#include <cuda_bf16.h>
#include <cstdint>

// MultiHeadDenseSynthesizer: B=64, L=500, F=256, H=4, dk=64
// Round 11: pure-bf16 1-term MMA everywhere (error budget spend),
// k_final M=64/N-split (occ 12.5->25%), k_attn M=128 tiles.

#define BB  64
#define LL  500
#define FF  256
#define HH  4
#define DKK 64
#define BLL (BB*LL)
#define BH  (BB*HH)
#define LPAD 512

// ---------------- device scratch (zero-initialized at load) ----------------
__device__ float g_ctx[BLL*FF];
__device__ uint4 g_wt_h4[BH*LL*DKK/8];     // W  [bh][l][d] bf16
__device__ uint4 g_vT_h4[BH*DKK*LPAD/8];   // Vt [bh][d][j] bf16
__device__ uint4 g_w2T_h4[LPAD*DKK/8];     // w2T [j][d] bf16
__device__ uint4 g_wqsT4h[FF*FF/8];        // [n][k] bf16
__device__ uint4 g_wvsT4h[FF*FF/8];
__device__ uint4 g_fcwT4h[FF*FF/8];
__device__ uint4 g_w1T4h[DKK*DKK/8];

__device__ __forceinline__ uint32_t pack_hi2(float x, float y) {
    __nv_bfloat162 t = __float22bfloat162_rn(make_float2(x, y));
    return *(uint32_t*)&t;
}
__device__ __forceinline__ void mma16816(float c[4], const uint32_t a[4], const uint32_t b[2]) {
    asm volatile(
        "mma.sync.aligned.m16n8k16.row.col.f32.bf16.bf16.f32 "
        "{%0,%1,%2,%3}, {%4,%5,%6,%7}, {%8,%9}, {%0,%1,%2,%3};"
        : "+f"(c[0]), "+f"(c[1]), "+f"(c[2]), "+f"(c[3])
        : "r"(a[0]), "r"(a[1]), "r"(a[2]), "r"(a[3]), "r"(b[0]), "r"(b[1]));
}

// ---------------------------------------------------------------------------
// k_prep_all: all weight transposes -> bf16 (hi only).
// blocks [0,128): w2T, [128,384): wqsT, [384,640): wvsT, [640,896): fcwT,
// [896,912): w1T.
// ---------------------------------------------------------------------------
__global__ void k_prep_all(const float* __restrict__ w2, const float* __restrict__ wqs,
                           const float* __restrict__ wvs, const float* __restrict__ fcw,
                           const float* __restrict__ w1)
{
    int bx = blockIdx.x, tid = threadIdx.x;
    float v; __nv_bfloat16* dh; int idx;
    if (bx < 128) {
        idx = bx*256 + tid;                       // j*64 + d
        int j = idx >> 6, d = idx & 63;
        v = (j < LL) ? w2[d*LL + j] : 0.f;
        dh = (__nv_bfloat16*)g_w2T_h4;
    } else if (bx < 384) {
        idx = (bx - 128)*256 + tid;               // n*256 + k
        int n = idx >> 8, k = idx & 255;
        v = wqs[k*FF + n];
        dh = (__nv_bfloat16*)g_wqsT4h;
    } else if (bx < 640) {
        idx = (bx - 384)*256 + tid;
        int n = idx >> 8, k = idx & 255;
        v = wvs[k*FF + n];
        dh = (__nv_bfloat16*)g_wvsT4h;
    } else if (bx < 896) {
        idx = (bx - 640)*256 + tid;
        int n = idx >> 8, k = idx & 255;
        v = fcw[k*FF + n];
        dh = (__nv_bfloat16*)g_fcwT4h;
    } else {
        idx = (bx - 896)*256 + tid;               // n*64 + k
        int n = idx >> 6, k = idx & 63;
        v = w1[k*DKK + n];
        dh = (__nv_bfloat16*)g_w1T4h;
    }
    dh[idx] = __float2bfloat16(v);
}

// ---------------------------------------------------------------------------
// Kernel 1: projections via mma.sync (1-term). grid (250, 4, 2), 256 thr.
// ---------------------------------------------------------------------------
#define PJ_WPITCH 528
#define PJ_W1OFF  (64*PJ_WPITCH)            // 33792
#define PJ_B1OFF  (PJ_W1OFF + 64*144)       // 43008
#define PJ_SMEM   (PJ_B1OFF + 256)          // 43264

__global__ void __launch_bounds__(256)
k_proj_mma(const float* __restrict__ qin, const float* __restrict__ vin,
           const float* __restrict__ b1)
{
    extern __shared__ char smem[];
    char* sWh  = smem;
    char* sW1h = smem + PJ_W1OFF;
    float* b1s = (float*)(smem + PJ_B1OFF);
    float* vtr = (float*)smem;          // mode1 alias: [64][132] fp32 (33792 B)

    const int tid  = threadIdx.x;
    const int lane = tid & 31, wid = tid >> 5;
    const int g4 = lane >> 2, t4 = lane & 3;
    const int m0 = blockIdx.x * 128;
    const int h  = blockIdx.y;
    const int mode = blockIdx.z;
    const float* A = mode ? vin : qin;
    const uint4* WTh = mode ? g_wvsT4h : g_wqsT4h;

    for (int idx = tid; idx < 2048; idx += 256) {
        int row = idx >> 5, c16 = idx & 31;
        *(uint4*)(sWh + row*PJ_WPITCH + c16*16) = WTh[(h*64 + row)*32 + c16];
    }
    if (!mode) {
        for (int idx = tid; idx < 512; idx += 256) {
            int row = idx >> 3, gq = idx & 7;
            *(uint4*)(sW1h + row*144 + gq*16) = g_w1T4h[row*8 + gq];
        }
        if (tid < 64) b1s[tid] = b1[tid];
    }
    __syncthreads();

    const int r0 = wid*16 + g4;
    const int gr0 = m0 + r0, gr1 = gr0 + 8;

    float sacc[8][4];
#pragma unroll
    for (int nt = 0; nt < 8; nt++)
#pragma unroll
        for (int e = 0; e < 4; e++) sacc[nt][e] = 0.f;

#pragma unroll 4
    for (int kt = 0; kt < 16; kt++) {
        int c0 = kt*16 + t4*2;
        uint32_t ah[4];
        float2 f;
        f = *(const float2*)(A + (size_t)gr0*FF + c0);     ah[0] = pack_hi2(f.x, f.y);
        f = *(const float2*)(A + (size_t)gr1*FF + c0);     ah[1] = pack_hi2(f.x, f.y);
        f = *(const float2*)(A + (size_t)gr0*FF + c0 + 8); ah[2] = pack_hi2(f.x, f.y);
        f = *(const float2*)(A + (size_t)gr1*FF + c0 + 8); ah[3] = pack_hi2(f.x, f.y);
#pragma unroll
        for (int nt = 0; nt < 8; nt++) {
            int off = (nt*8 + g4)*PJ_WPITCH + c0*2;
            uint32_t bh2[2];
            bh2[0] = *(const uint32_t*)(sWh + off);
            bh2[1] = *(const uint32_t*)(sWh + off + 16);
            mma16816(sacc[nt], ah, bh2);
        }
    }

    if (mode) {
        // ---- transpose vh via smem -> g_vT [bh][d][j] bf16
        __syncthreads();
#pragma unroll
        for (int nt = 0; nt < 8; nt++) {
            int d0 = nt*8 + t4*2;
            vtr[d0*132 + r0]         = sacc[nt][0];
            vtr[(d0+1)*132 + r0]     = sacc[nt][1];
            vtr[d0*132 + r0 + 8]     = sacc[nt][2];
            vtr[(d0+1)*132 + r0 + 8] = sacc[nt][3];
        }
        __syncthreads();
        __nv_bfloat16* vTh = (__nv_bfloat16*)g_vT_h4;
        for (int idx = tid; idx < 4096; idx += 256) {
            int d = idx >> 6, jp = idx & 63;
            int gj = m0 + 2*jp;
            int b = gj / LL, p = gj - b*LL;   // pairs never cross batch (500 even)
            size_t a = ((size_t)((b*HH + h)*DKK + d))*LPAD + p;
            *(uint32_t*)(vTh + a) = pack_hi2(vtr[d*132 + 2*jp], vtr[d*132 + 2*jp + 1]);
        }
        return;
    }

    // ---- hand-off: qh C-frags -> A-frags
    uint32_t ph[4][4];
#pragma unroll
    for (int nt = 0; nt < 8; nt++) {
        int kt = nt >> 1, i0 = (nt & 1) * 2;
        ph[kt][i0]     = pack_hi2(sacc[nt][0], sacc[nt][1]);
        ph[kt][i0 + 1] = pack_hi2(sacc[nt][2], sacc[nt][3]);
    }

    float s2[8][4];
#pragma unroll
    for (int nt = 0; nt < 8; nt++) {
        int col = nt*8 + t4*2;
        s2[nt][0] = s2[nt][2] = b1s[col];
        s2[nt][1] = s2[nt][3] = b1s[col + 1];
    }
#pragma unroll
    for (int kt = 0; kt < 4; kt++) {
#pragma unroll
        for (int nt = 0; nt < 8; nt++) {
            int off = (nt*8 + g4)*144 + (kt*16 + t4*2)*2;
            uint32_t bh2[2];
            bh2[0] = *(const uint32_t*)(sW1h + off);
            bh2[1] = *(const uint32_t*)(sW1h + off + 16);
            mma16816(s2[nt], ph[kt], bh2);
        }
    }

    // relu + store g_wt (bf16)
    __nv_bfloat16* wth = (__nv_bfloat16*)g_wt_h4;
    int b0_ = gr0 / LL, l0_ = gr0 - b0_*LL;
    int b1_ = gr1 / LL, l1_ = gr1 - b1_*LL;
    size_t base0 = ((size_t)((b0_*HH + h)*LL + l0_))*DKK;
    size_t base1 = ((size_t)((b1_*HH + h)*LL + l1_))*DKK;
#pragma unroll
    for (int nt = 0; nt < 8; nt++) {
        int d = nt*8 + t4*2;
        *(uint32_t*)(wth + base0 + d) =
            pack_hi2(fmaxf(s2[nt][0], 0.f), fmaxf(s2[nt][1], 0.f));
        *(uint32_t*)(wth + base1 + d) =
            pack_hi2(fmaxf(s2[nt][2], 0.f), fmaxf(s2[nt][3], 0.f));
    }
}

// ---------------------------------------------------------------------------
// Kernel 2: mma.sync attention (1-term). grid (4, H, B), 256 thr, M=128 tile.
// ---------------------------------------------------------------------------
#define SPITCH 144

__global__ void __launch_bounds__(256)
k_attn_mma(const float* __restrict__ b2)
{
    __shared__ float b2s[64];
    __shared__ __align__(16) char sW2h[64*SPITCH];
    __shared__ __align__(16) char sVh [64*SPITCH];

    const int tid  = threadIdx.x;
    const int lane = tid & 31, wid = tid >> 5;
    const int g4 = lane >> 2, t4 = lane & 3;
    const int l0 = blockIdx.x * 128;
    const int h  = blockIdx.y, b = blockIdx.z;
    const int bh = b*HH + h;
    const int r0 = l0 + wid*16 + g4;

    const __nv_bfloat16* wth = (const __nv_bfloat16*)g_wt_h4;

    uint32_t aWh[4][4];
    {
        const bool v0 = (r0 < LL), v1 = (r0 + 8 < LL);
        size_t base0 = (size_t)(bh*LL + r0)*DKK;
        size_t base1 = (size_t)(bh*LL + r0 + 8)*DKK;
#pragma unroll
        for (int kt = 0; kt < 4; kt++) {
            int c0 = kt*16 + t4*2, c8 = c0 + 8;
            aWh[kt][0] = v0 ? *(const uint32_t*)(wth + base0 + c0) : 0u;
            aWh[kt][1] = v1 ? *(const uint32_t*)(wth + base1 + c0) : 0u;
            aWh[kt][2] = v0 ? *(const uint32_t*)(wth + base0 + c8) : 0u;
            aWh[kt][3] = v1 ? *(const uint32_t*)(wth + base1 + c8) : 0u;
        }
    }

    float oacc[8][4];
#pragma unroll
    for (int nt = 0; nt < 8; nt++)
#pragma unroll
        for (int e = 0; e < 4; e++) oacc[nt][e] = 0.f;
    float dp0 = 0.f, dp1 = 0.f;

    for (int c = 0; c < 8; c++) {
        const int j0 = c * 64;
        __syncthreads();
#pragma unroll
        for (int it = 0; it < 2; it++) {
            int idx = tid + it*256;
            int row = idx >> 3, gq = idx & 7;
            *(uint4*)(sW2h + row*SPITCH + gq*16) = g_w2T_h4[(size_t)(j0 + row)*8 + gq];
            size_t sv = (size_t)(bh*DKK + row)*(LPAD/8) + (j0 >> 3) + gq;
            *(uint4*)(sVh + row*SPITCH + gq*16) = g_vT_h4[sv];
        }
        if (tid < 64) b2s[tid] = (j0 + tid < LL) ? b2[j0 + tid] : 0.f;
        __syncthreads();

        float sacc[8][4];
#pragma unroll
        for (int nt = 0; nt < 8; nt++)
#pragma unroll
            for (int e = 0; e < 4; e++) sacc[nt][e] = 0.f;

#pragma unroll
        for (int kt = 0; kt < 4; kt++) {
#pragma unroll
            for (int nt = 0; nt < 8; nt++) {
                int off = (nt*8 + g4)*SPITCH + (kt*16 + t4*2)*2;
                uint32_t bh2[2];
                bh2[0] = *(const uint32_t*)(sW2h + off);
                bh2[1] = *(const uint32_t*)(sW2h + off + 16);
                mma16816(sacc[nt], aWh[kt], bh2);
            }
        }

        uint32_t phA[4][4];
#pragma unroll
        for (int nt = 0; nt < 8; nt++) {
            int jl = nt*8 + t4*2;
            int jg = j0 + jl;
            float bb0 = b2s[jl], bb1 = b2s[jl + 1];
            float p0 = (jg     < LL) ? __expf(sacc[nt][0] + bb0) : 0.f;
            float p1 = (jg + 1 < LL) ? __expf(sacc[nt][1] + bb1) : 0.f;
            float p2 = (jg     < LL) ? __expf(sacc[nt][2] + bb0) : 0.f;
            float p3 = (jg + 1 < LL) ? __expf(sacc[nt][3] + bb1) : 0.f;
            dp0 += p0 + p1;
            dp1 += p2 + p3;
            int kt = nt >> 1, i0 = (nt & 1) * 2;
            phA[kt][i0]     = pack_hi2(p0, p1);
            phA[kt][i0 + 1] = pack_hi2(p2, p3);
        }

#pragma unroll
        for (int kt = 0; kt < 4; kt++) {
#pragma unroll
            for (int nt = 0; nt < 8; nt++) {
                int off = (nt*8 + g4)*SPITCH + (kt*16 + t4*2)*2;
                uint32_t bvh[2];
                bvh[0] = *(const uint32_t*)(sVh + off);
                bvh[1] = *(const uint32_t*)(sVh + off + 16);
                mma16816(oacc[nt], phA[kt], bvh);
            }
        }
    }

    dp0 += __shfl_xor_sync(0xffffffffu, dp0, 1);
    dp0 += __shfl_xor_sync(0xffffffffu, dp0, 2);
    dp1 += __shfl_xor_sync(0xffffffffu, dp1, 1);
    dp1 += __shfl_xor_sync(0xffffffffu, dp1, 2);
    float inv0 = 1.f / dp0, inv1 = 1.f / dp1;

    if (r0 < LL) {
        float* dst = g_ctx + ((size_t)(b*LL + r0))*FF + h*DKK + t4*2;
#pragma unroll
        for (int nt = 0; nt < 8; nt++) {
            float2 v; v.x = oacc[nt][0]*inv0; v.y = oacc[nt][1]*inv0;
            *(float2*)(dst + nt*8) = v;
        }
    }
    if (r0 + 8 < LL) {
        float* dst = g_ctx + ((size_t)(b*LL + r0 + 8))*FF + h*DKK + t4*2;
#pragma unroll
        for (int nt = 0; nt < 8; nt++) {
            float2 v; v.x = oacc[nt][2]*inv1; v.y = oacc[nt][3]*inv1;
            *(float2*)(dst + nt*8) = v;
        }
    }
}

// ---------------------------------------------------------------------------
// Kernel 3: out = LN(ctx @ fcwT^T + q). grid 500 (M=64/CTA), 256 thr.
// Warp w: rows (w&3)*16..+16, cols (w>>2)*128..+128. LN combines the two
// column halves via smem.
// ---------------------------------------------------------------------------
#define FN_SMEM (256*144)   // 36864

__global__ void __launch_bounds__(256)
k_final_mma(const float* __restrict__ qin, const float* __restrict__ lng,
            const float* __restrict__ lnb, float* __restrict__ out)
{
    extern __shared__ char smem[];
    char* sFh = smem;
    __shared__ float red_s[64][2], red_q[64][2];

    const int tid  = threadIdx.x;
    const int lane = tid & 31, wid = tid >> 5;
    const int g4 = lane >> 2, t4 = lane & 3;
    const int half = wid >> 2, wrow = wid & 3;
    const int ncol0 = half * 128;
    const int m0 = blockIdx.x * 64;
    const int r0 = wrow*16 + g4;
    const int gr0 = m0 + r0, gr1 = gr0 + 8;

    float sacc[16][4];
#pragma unroll
    for (int nt = 0; nt < 16; nt++)
#pragma unroll
        for (int e = 0; e < 4; e++) sacc[nt][e] = 0.f;

    for (int kc = 0; kc < 4; kc++) {
        __syncthreads();
        for (int idx = tid; idx < 2048; idx += 256) {
            int row = idx >> 3, gq = idx & 7;
            *(uint4*)(sFh + row*144 + gq*16) = g_fcwT4h[row*32 + kc*8 + gq];
        }
        __syncthreads();

#pragma unroll
        for (int kt = 0; kt < 4; kt++) {
            int cg = kc*64 + kt*16 + t4*2;
            uint32_t ah[4];
            float2 f;
            f = *(const float2*)(g_ctx + (size_t)gr0*FF + cg);     ah[0] = pack_hi2(f.x, f.y);
            f = *(const float2*)(g_ctx + (size_t)gr1*FF + cg);     ah[1] = pack_hi2(f.x, f.y);
            f = *(const float2*)(g_ctx + (size_t)gr0*FF + cg + 8); ah[2] = pack_hi2(f.x, f.y);
            f = *(const float2*)(g_ctx + (size_t)gr1*FF + cg + 8); ah[3] = pack_hi2(f.x, f.y);
            int koff = (kt*16 + t4*2)*2;
#pragma unroll
            for (int nt = 0; nt < 16; nt++) {
                int off = (ncol0 + nt*8 + g4)*144 + koff;
                uint32_t bh2[2];
                bh2[0] = *(const uint32_t*)(sFh + off);
                bh2[1] = *(const uint32_t*)(sFh + off + 16);
                mma16816(sacc[nt], ah, bh2);
            }
        }
    }

    // residual + LN partial stats (this thread: 32 cols of its half, 2 rows)
    float sum0 = 0.f, sq0 = 0.f, sum1 = 0.f, sq1 = 0.f;
#pragma unroll
    for (int nt = 0; nt < 16; nt++) {
        int col = ncol0 + nt*8 + t4*2;
        float2 q0 = *(const float2*)(qin + (size_t)gr0*FF + col);
        float2 q1 = *(const float2*)(qin + (size_t)gr1*FF + col);
        sacc[nt][0] += q0.x; sacc[nt][1] += q0.y;
        sacc[nt][2] += q1.x; sacc[nt][3] += q1.y;
        sum0 += sacc[nt][0] + sacc[nt][1];
        sq0  += sacc[nt][0]*sacc[nt][0] + sacc[nt][1]*sacc[nt][1];
        sum1 += sacc[nt][2] + sacc[nt][3];
        sq1  += sacc[nt][2]*sacc[nt][2] + sacc[nt][3]*sacc[nt][3];
    }
    sum0 += __shfl_xor_sync(0xffffffffu, sum0, 1);
    sum0 += __shfl_xor_sync(0xffffffffu, sum0, 2);
    sq0  += __shfl_xor_sync(0xffffffffu, sq0, 1);
    sq0  += __shfl_xor_sync(0xffffffffu, sq0, 2);
    sum1 += __shfl_xor_sync(0xffffffffu, sum1, 1);
    sum1 += __shfl_xor_sync(0xffffffffu, sum1, 2);
    sq1  += __shfl_xor_sync(0xffffffffu, sq1, 1);
    sq1  += __shfl_xor_sync(0xffffffffu, sq1, 2);

    __syncthreads();   // sFh reads done; also order red_* writes
    if (t4 == 0) {
        red_s[r0][half] = sum0;     red_q[r0][half] = sq0;
        red_s[r0 + 8][half] = sum1; red_q[r0 + 8][half] = sq1;
    }
    __syncthreads();

    float s0 = red_s[r0][0] + red_s[r0][1];
    float qq0 = red_q[r0][0] + red_q[r0][1];
    float s1 = red_s[r0 + 8][0] + red_s[r0 + 8][1];
    float qq1 = red_q[r0 + 8][0] + red_q[r0 + 8][1];

    float mu0 = s0 * (1.f/256.f);
    float mu1 = s1 * (1.f/256.f);
    float rstd0 = rsqrtf(qq0 * (1.f/256.f) - mu0*mu0 + 1e-6f);
    float rstd1 = rsqrtf(qq1 * (1.f/256.f) - mu1*mu1 + 1e-6f);

#pragma unroll
    for (int nt = 0; nt < 16; nt++) {
        int col = ncol0 + nt*8 + t4*2;
        float2 g = *(const float2*)(lng + col);
        float2 bt = *(const float2*)(lnb + col);
        float2 o0, o1;
        o0.x = (sacc[nt][0] - mu0)*rstd0*g.x + bt.x;
        o0.y = (sacc[nt][1] - mu0)*rstd0*g.y + bt.y;
        o1.x = (sacc[nt][2] - mu1)*rstd1*g.x + bt.x;
        o1.y = (sacc[nt][3] - mu1)*rstd1*g.y + bt.y;
        *(float2*)(out + (size_t)gr0*FF + col) = o0;
        *(float2*)(out + (size_t)gr1*FF + col) = o1;
    }
}

// ---------------------------------------------------------------------------
extern "C" void kernel_launch(void* const* d_in, const int* in_sizes, int n_in,
                              void* d_out, int out_size)
{
    const float* q    = (const float*)d_in[0];
    const float* v    = (const float*)d_in[2];   // d_in[1] (k) unused by model
    const float* w_qs = (const float*)d_in[3];
    const float* w_vs = (const float*)d_in[4];
    const float* w1   = (const float*)d_in[5];
    const float* b1   = (const float*)d_in[6];
    const float* w2   = (const float*)d_in[7];
    const float* b2   = (const float*)d_in[8];
    const float* fcw  = (const float*)d_in[9];
    const float* lng  = (const float*)d_in[10];
    const float* lnb  = (const float*)d_in[11];
    float* out = (float*)d_out;

    cudaFuncSetAttribute(k_proj_mma,  cudaFuncAttributeMaxDynamicSharedMemorySize, PJ_SMEM);
    cudaFuncSetAttribute(k_final_mma, cudaFuncAttributeMaxDynamicSharedMemorySize, FN_SMEM);

    k_prep_all <<<912, 256>>>(w2, w_qs, w_vs, fcw, w1);
    k_proj_mma <<<dim3(250, HH, 2), 256, PJ_SMEM>>>(q, v, b1);
    k_attn_mma <<<dim3(4, HH, BB),  256>>>(b2);
    k_final_mma<<<500,              256, FN_SMEM>>>(q, lng, lnb, out);
}

// round 12
// speedup vs baseline: 4.7178x; 1.0895x over previous
#include <cuda_runtime.h>
#include <cuda_bf16.h>
#include <cstdint>

// MultiHeadDenseSynthesizer: B=64, L=500, F=256, H=4, dk=64
// Round 12: bf16 ctx in A-frag layout; cp.async double-buffered staging
// in attn + final. Pure-bf16 1-term MMA (validated round 11).

#define BB  64
#define LL  500
#define FF  256
#define HH  4
#define DKK 64
#define BLL (BB*LL)
#define BH  (BB*HH)
#define LPAD 512

// ---------------- device scratch (zero-initialized at load) ----------------
__device__ __nv_bfloat16 g_ctxb[BLL*FF];   // attn out, bf16, [b*L+l][f]
__device__ uint4 g_wt_h4[BH*LL*DKK/8];     // W  [bh][l][d] bf16
__device__ uint4 g_vT_h4[BH*DKK*LPAD/8];   // Vt [bh][d][j] bf16
__device__ uint4 g_w2T_h4[LPAD*DKK/8];     // w2T [j][d] bf16
__device__ uint4 g_wqsT4h[FF*FF/8];        // [n][k] bf16
__device__ uint4 g_wvsT4h[FF*FF/8];
__device__ uint4 g_fcwT4h[FF*FF/8];
__device__ uint4 g_w1T4h[DKK*DKK/8];

__device__ __forceinline__ uint32_t pack_hi2(float x, float y) {
    __nv_bfloat162 t = __float22bfloat162_rn(make_float2(x, y));
    return *(uint32_t*)&t;
}
__device__ __forceinline__ void mma16816(float c[4], const uint32_t a[4], const uint32_t b[2]) {
    asm volatile(
        "mma.sync.aligned.m16n8k16.row.col.f32.bf16.bf16.f32 "
        "{%0,%1,%2,%3}, {%4,%5,%6,%7}, {%8,%9}, {%0,%1,%2,%3};"
        : "+f"(c[0]), "+f"(c[1]), "+f"(c[2]), "+f"(c[3])
        : "r"(a[0]), "r"(a[1]), "r"(a[2]), "r"(a[3]), "r"(b[0]), "r"(b[1]));
}
__device__ __forceinline__ void cpa16(uint32_t s, const void* g) {
    asm volatile("cp.async.cg.shared.global [%0], [%1], 16;" :: "r"(s), "l"(g));
}
#define CPA_COMMIT() asm volatile("cp.async.commit_group;" ::: "memory")
#define CPA_WAIT0()  asm volatile("cp.async.wait_group 0;"  ::: "memory")

// ---------------------------------------------------------------------------
// k_prep_all: all weight transposes -> bf16.
// blocks [0,128): w2T, [128,384): wqsT, [384,640): wvsT, [640,896): fcwT,
// [896,912): w1T.
// ---------------------------------------------------------------------------
__global__ void k_prep_all(const float* __restrict__ w2, const float* __restrict__ wqs,
                           const float* __restrict__ wvs, const float* __restrict__ fcw,
                           const float* __restrict__ w1)
{
    int bx = blockIdx.x, tid = threadIdx.x;
    float v; __nv_bfloat16* dh; int idx;
    if (bx < 128) {
        idx = bx*256 + tid;                       // j*64 + d
        int j = idx >> 6, d = idx & 63;
        v = (j < LL) ? w2[d*LL + j] : 0.f;
        dh = (__nv_bfloat16*)g_w2T_h4;
    } else if (bx < 384) {
        idx = (bx - 128)*256 + tid;               // n*256 + k
        int n = idx >> 8, k = idx & 255;
        v = wqs[k*FF + n];
        dh = (__nv_bfloat16*)g_wqsT4h;
    } else if (bx < 640) {
        idx = (bx - 384)*256 + tid;
        int n = idx >> 8, k = idx & 255;
        v = wvs[k*FF + n];
        dh = (__nv_bfloat16*)g_wvsT4h;
    } else if (bx < 896) {
        idx = (bx - 640)*256 + tid;
        int n = idx >> 8, k = idx & 255;
        v = fcw[k*FF + n];
        dh = (__nv_bfloat16*)g_fcwT4h;
    } else {
        idx = (bx - 896)*256 + tid;               // n*64 + k
        int n = idx >> 6, k = idx & 63;
        v = w1[k*DKK + n];
        dh = (__nv_bfloat16*)g_w1T4h;
    }
    dh[idx] = __float2bfloat16(v);
}

// ---------------------------------------------------------------------------
// Kernel 1: projections via mma.sync. grid (250, 4, 2), 256 thr.
// ---------------------------------------------------------------------------
#define PJ_WPITCH 528
#define PJ_W1OFF  (64*PJ_WPITCH)            // 33792
#define PJ_B1OFF  (PJ_W1OFF + 64*144)       // 43008
#define PJ_SMEM   (PJ_B1OFF + 256)          // 43264

__global__ void __launch_bounds__(256)
k_proj_mma(const float* __restrict__ qin, const float* __restrict__ vin,
           const float* __restrict__ b1)
{
    extern __shared__ char smem[];
    char* sWh  = smem;
    char* sW1h = smem + PJ_W1OFF;
    float* b1s = (float*)(smem + PJ_B1OFF);
    float* vtr = (float*)smem;          // mode1 alias: [64][132] fp32

    const int tid  = threadIdx.x;
    const int lane = tid & 31, wid = tid >> 5;
    const int g4 = lane >> 2, t4 = lane & 3;
    const int m0 = blockIdx.x * 128;
    const int h  = blockIdx.y;
    const int mode = blockIdx.z;
    const float* A = mode ? vin : qin;
    const uint4* WTh = mode ? g_wvsT4h : g_wqsT4h;

    for (int idx = tid; idx < 2048; idx += 256) {
        int row = idx >> 5, c16 = idx & 31;
        *(uint4*)(sWh + row*PJ_WPITCH + c16*16) = WTh[(h*64 + row)*32 + c16];
    }
    if (!mode) {
        for (int idx = tid; idx < 512; idx += 256) {
            int row = idx >> 3, gq = idx & 7;
            *(uint4*)(sW1h + row*144 + gq*16) = g_w1T4h[row*8 + gq];
        }
        if (tid < 64) b1s[tid] = b1[tid];
    }
    __syncthreads();

    const int r0 = wid*16 + g4;
    const int gr0 = m0 + r0, gr1 = gr0 + 8;

    float sacc[8][4];
#pragma unroll
    for (int nt = 0; nt < 8; nt++)
#pragma unroll
        for (int e = 0; e < 4; e++) sacc[nt][e] = 0.f;

#pragma unroll 4
    for (int kt = 0; kt < 16; kt++) {
        int c0 = kt*16 + t4*2;
        uint32_t ah[4];
        float2 f;
        f = *(const float2*)(A + (size_t)gr0*FF + c0);     ah[0] = pack_hi2(f.x, f.y);
        f = *(const float2*)(A + (size_t)gr1*FF + c0);     ah[1] = pack_hi2(f.x, f.y);
        f = *(const float2*)(A + (size_t)gr0*FF + c0 + 8); ah[2] = pack_hi2(f.x, f.y);
        f = *(const float2*)(A + (size_t)gr1*FF + c0 + 8); ah[3] = pack_hi2(f.x, f.y);
#pragma unroll
        for (int nt = 0; nt < 8; nt++) {
            int off = (nt*8 + g4)*PJ_WPITCH + c0*2;
            uint32_t bh2[2];
            bh2[0] = *(const uint32_t*)(sWh + off);
            bh2[1] = *(const uint32_t*)(sWh + off + 16);
            mma16816(sacc[nt], ah, bh2);
        }
    }

    if (mode) {
        // ---- transpose vh via smem -> g_vT [bh][d][j] bf16
        __syncthreads();
#pragma unroll
        for (int nt = 0; nt < 8; nt++) {
            int d0 = nt*8 + t4*2;
            vtr[d0*132 + r0]         = sacc[nt][0];
            vtr[(d0+1)*132 + r0]     = sacc[nt][1];
            vtr[d0*132 + r0 + 8]     = sacc[nt][2];
            vtr[(d0+1)*132 + r0 + 8] = sacc[nt][3];
        }
        __syncthreads();
        __nv_bfloat16* vTh = (__nv_bfloat16*)g_vT_h4;
        for (int idx = tid; idx < 4096; idx += 256) {
            int d = idx >> 6, jp = idx & 63;
            int gj = m0 + 2*jp;
            int b = gj / LL, p = gj - b*LL;   // pairs never cross batch (500 even)
            size_t a = ((size_t)((b*HH + h)*DKK + d))*LPAD + p;
            *(uint32_t*)(vTh + a) = pack_hi2(vtr[d*132 + 2*jp], vtr[d*132 + 2*jp + 1]);
        }
        return;
    }

    // ---- hand-off: qh C-frags -> A-frags
    uint32_t ph[4][4];
#pragma unroll
    for (int nt = 0; nt < 8; nt++) {
        int kt = nt >> 1, i0 = (nt & 1) * 2;
        ph[kt][i0]     = pack_hi2(sacc[nt][0], sacc[nt][1]);
        ph[kt][i0 + 1] = pack_hi2(sacc[nt][2], sacc[nt][3]);
    }

    float s2[8][4];
#pragma unroll
    for (int nt = 0; nt < 8; nt++) {
        int col = nt*8 + t4*2;
        s2[nt][0] = s2[nt][2] = b1s[col];
        s2[nt][1] = s2[nt][3] = b1s[col + 1];
    }
#pragma unroll
    for (int kt = 0; kt < 4; kt++) {
#pragma unroll
        for (int nt = 0; nt < 8; nt++) {
            int off = (nt*8 + g4)*144 + (kt*16 + t4*2)*2;
            uint32_t bh2[2];
            bh2[0] = *(const uint32_t*)(sW1h + off);
            bh2[1] = *(const uint32_t*)(sW1h + off + 16);
            mma16816(s2[nt], ph[kt], bh2);
        }
    }

    // relu + store g_wt (bf16)
    __nv_bfloat16* wth = (__nv_bfloat16*)g_wt_h4;
    int b0_ = gr0 / LL, l0_ = gr0 - b0_*LL;
    int b1_ = gr1 / LL, l1_ = gr1 - b1_*LL;
    size_t base0 = ((size_t)((b0_*HH + h)*LL + l0_))*DKK;
    size_t base1 = ((size_t)((b1_*HH + h)*LL + l1_))*DKK;
#pragma unroll
    for (int nt = 0; nt < 8; nt++) {
        int d = nt*8 + t4*2;
        *(uint32_t*)(wth + base0 + d) =
            pack_hi2(fmaxf(s2[nt][0], 0.f), fmaxf(s2[nt][1], 0.f));
        *(uint32_t*)(wth + base1 + d) =
            pack_hi2(fmaxf(s2[nt][2], 0.f), fmaxf(s2[nt][3], 0.f));
    }
}

// ---------------------------------------------------------------------------
// Kernel 2: attention, cp.async double-buffered. grid (4, H, B), 256 thr.
// ---------------------------------------------------------------------------
#define SPITCH 144
#define ATILE (64*SPITCH)   // 9216

__global__ void __launch_bounds__(256)
k_attn_mma(const float* __restrict__ b2)
{
    __shared__ float b2all[512];
    __shared__ __align__(16) char sW2[2][ATILE];
    __shared__ __align__(16) char sV [2][ATILE];

    const int tid  = threadIdx.x;
    const int lane = tid & 31, wid = tid >> 5;
    const int g4 = lane >> 2, t4 = lane & 3;
    const int l0 = blockIdx.x * 128;
    const int h  = blockIdx.y, b = blockIdx.z;
    const int bh = b*HH + h;
    const int r0 = l0 + wid*16 + g4;

    const uint32_t sW2a = (uint32_t)__cvta_generic_to_shared(sW2);
    const uint32_t sVa  = (uint32_t)__cvta_generic_to_shared(sV);

#pragma unroll
    for (int it = 0; it < 2; it++) {
        int i = tid + it*256;
        b2all[i] = (i < LL) ? b2[i] : 0.f;
    }

    const __nv_bfloat16* wth = (const __nv_bfloat16*)g_wt_h4;
    uint32_t aWh[4][4];
    {
        const bool v0 = (r0 < LL), v1 = (r0 + 8 < LL);
        size_t base0 = (size_t)(bh*LL + r0)*DKK;
        size_t base1 = (size_t)(bh*LL + r0 + 8)*DKK;
#pragma unroll
        for (int kt = 0; kt < 4; kt++) {
            int c0 = kt*16 + t4*2, c8 = c0 + 8;
            aWh[kt][0] = v0 ? *(const uint32_t*)(wth + base0 + c0) : 0u;
            aWh[kt][1] = v1 ? *(const uint32_t*)(wth + base1 + c0) : 0u;
            aWh[kt][2] = v0 ? *(const uint32_t*)(wth + base0 + c8) : 0u;
            aWh[kt][3] = v1 ? *(const uint32_t*)(wth + base1 + c8) : 0u;
        }
    }

    float oacc[8][4];
#pragma unroll
    for (int nt = 0; nt < 8; nt++)
#pragma unroll
        for (int e = 0; e < 4; e++) oacc[nt][e] = 0.f;
    float dp0 = 0.f, dp1 = 0.f;

    // stage chunk 0 into buffer 0
    {
        const int row = tid >> 3, gq = tid & 7;   // plus second half
#pragma unroll
        for (int it = 0; it < 2; it++) {
            int idx = tid + it*256;
            int rr = idx >> 3, gg = idx & 7;
            cpa16(sW2a + rr*SPITCH + gg*16, &g_w2T_h4[(size_t)rr*8 + gg]);
            cpa16(sVa  + rr*SPITCH + gg*16,
                  &g_vT_h4[(size_t)(bh*DKK + rr)*(LPAD/8) + gg]);
        }
        (void)row; (void)gq;
    }
    CPA_COMMIT();

    for (int c = 0; c < 8; c++) {
        const int j0 = c * 64;
        const int buf = c & 1;
        CPA_WAIT0();
        __syncthreads();
        if (c < 7) {
            const int jn = (c + 1) * 64;
            const uint32_t dW2 = sW2a + (buf ^ 1)*ATILE;
            const uint32_t dV  = sVa  + (buf ^ 1)*ATILE;
#pragma unroll
            for (int it = 0; it < 2; it++) {
                int idx = tid + it*256;
                int rr = idx >> 3, gg = idx & 7;
                cpa16(dW2 + rr*SPITCH + gg*16, &g_w2T_h4[(size_t)(jn + rr)*8 + gg]);
                cpa16(dV  + rr*SPITCH + gg*16,
                      &g_vT_h4[(size_t)(bh*DKK + rr)*(LPAD/8) + (jn >> 3) + gg]);
            }
            CPA_COMMIT();
        }

        const char* w2b = sW2[buf];
        const char* vb  = sV[buf];

        float sacc[8][4];
#pragma unroll
        for (int nt = 0; nt < 8; nt++)
#pragma unroll
            for (int e = 0; e < 4; e++) sacc[nt][e] = 0.f;

#pragma unroll
        for (int kt = 0; kt < 4; kt++) {
#pragma unroll
            for (int nt = 0; nt < 8; nt++) {
                int off = (nt*8 + g4)*SPITCH + (kt*16 + t4*2)*2;
                uint32_t bh2[2];
                bh2[0] = *(const uint32_t*)(w2b + off);
                bh2[1] = *(const uint32_t*)(w2b + off + 16);
                mma16816(sacc[nt], aWh[kt], bh2);
            }
        }

        uint32_t phA[4][4];
#pragma unroll
        for (int nt = 0; nt < 8; nt++) {
            int jl = nt*8 + t4*2;
            int jg = j0 + jl;
            float bb0 = b2all[jg], bb1 = b2all[jg + 1];
            float p0 = (jg     < LL) ? __expf(sacc[nt][0] + bb0) : 0.f;
            float p1 = (jg + 1 < LL) ? __expf(sacc[nt][1] + bb1) : 0.f;
            float p2 = (jg     < LL) ? __expf(sacc[nt][2] + bb0) : 0.f;
            float p3 = (jg + 1 < LL) ? __expf(sacc[nt][3] + bb1) : 0.f;
            dp0 += p0 + p1;
            dp1 += p2 + p3;
            int kt = nt >> 1, i0 = (nt & 1) * 2;
            phA[kt][i0]     = pack_hi2(p0, p1);
            phA[kt][i0 + 1] = pack_hi2(p2, p3);
        }

#pragma unroll
        for (int kt = 0; kt < 4; kt++) {
#pragma unroll
            for (int nt = 0; nt < 8; nt++) {
                int off = (nt*8 + g4)*SPITCH + (kt*16 + t4*2)*2;
                uint32_t bvh[2];
                bvh[0] = *(const uint32_t*)(vb + off);
                bvh[1] = *(const uint32_t*)(vb + off + 16);
                mma16816(oacc[nt], phA[kt], bvh);
            }
        }
    }

    dp0 += __shfl_xor_sync(0xffffffffu, dp0, 1);
    dp0 += __shfl_xor_sync(0xffffffffu, dp0, 2);
    dp1 += __shfl_xor_sync(0xffffffffu, dp1, 1);
    dp1 += __shfl_xor_sync(0xffffffffu, dp1, 2);
    float inv0 = 1.f / dp0, inv1 = 1.f / dp1;

    // store ctx as bf16 pairs (A-frag layout for k_final)
    if (r0 < LL) {
        __nv_bfloat16* dst = g_ctxb + ((size_t)(b*LL + r0))*FF + h*DKK + t4*2;
#pragma unroll
        for (int nt = 0; nt < 8; nt++)
            *(uint32_t*)(dst + nt*8) = pack_hi2(oacc[nt][0]*inv0, oacc[nt][1]*inv0);
    }
    if (r0 + 8 < LL) {
        __nv_bfloat16* dst = g_ctxb + ((size_t)(b*LL + r0 + 8))*FF + h*DKK + t4*2;
#pragma unroll
        for (int nt = 0; nt < 8; nt++)
            *(uint32_t*)(dst + nt*8) = pack_hi2(oacc[nt][2]*inv1, oacc[nt][3]*inv1);
    }
}

// ---------------------------------------------------------------------------
// Kernel 3: out = LN(ctx @ fcwT^T + q). grid 500 (M=64/CTA), 256 thr.
// cp.async double-buffered fcw staging; bf16 ctx A-frags loaded directly.
// ---------------------------------------------------------------------------
#define FTILE (256*144)          // 36864
#define FN_SMEM (2*FTILE)        // 73728

__global__ void __launch_bounds__(256)
k_final_mma(const float* __restrict__ qin, const float* __restrict__ lng,
            const float* __restrict__ lnb, float* __restrict__ out)
{
    extern __shared__ char smem[];
    __shared__ float red_s[64][2], red_q[64][2];
    const uint32_t sFa = (uint32_t)__cvta_generic_to_shared(smem);

    const int tid  = threadIdx.x;
    const int lane = tid & 31, wid = tid >> 5;
    const int g4 = lane >> 2, t4 = lane & 3;
    const int half = wid >> 2, wrow = wid & 3;
    const int ncol0 = half * 128;
    const int m0 = blockIdx.x * 64;
    const int r0 = wrow*16 + g4;
    const int gr0 = m0 + r0, gr1 = gr0 + 8;
    const __nv_bfloat16* ctxb = g_ctxb;

    float sacc[16][4];
#pragma unroll
    for (int nt = 0; nt < 16; nt++)
#pragma unroll
        for (int e = 0; e < 4; e++) sacc[nt][e] = 0.f;

    // stage kc=0 into buffer 0
#pragma unroll
    for (int it = 0; it < 8; it++) {
        int idx = tid + it*256;
        int row = idx >> 3, gq = idx & 7;
        cpa16(sFa + row*144 + gq*16, &g_fcwT4h[row*32 + gq]);
    }
    CPA_COMMIT();

    for (int kc = 0; kc < 4; kc++) {
        const int buf = kc & 1;
        CPA_WAIT0();
        __syncthreads();
        if (kc < 3) {
            const uint32_t dF = sFa + (buf ^ 1)*FTILE;
#pragma unroll
            for (int it = 0; it < 8; it++) {
                int idx = tid + it*256;
                int row = idx >> 3, gq = idx & 7;
                cpa16(dF + row*144 + gq*16, &g_fcwT4h[row*32 + (kc+1)*8 + gq]);
            }
            CPA_COMMIT();
        }
        const char* sFh = smem + buf*FTILE;

#pragma unroll
        for (int kt = 0; kt < 4; kt++) {
            int cg = kc*64 + kt*16 + t4*2;
            uint32_t ah[4];
            ah[0] = *(const uint32_t*)(ctxb + (size_t)gr0*FF + cg);
            ah[1] = *(const uint32_t*)(ctxb + (size_t)gr1*FF + cg);
            ah[2] = *(const uint32_t*)(ctxb + (size_t)gr0*FF + cg + 8);
            ah[3] = *(const uint32_t*)(ctxb + (size_t)gr1*FF + cg + 8);
            int koff = (kt*16 + t4*2)*2;
#pragma unroll
            for (int nt = 0; nt < 16; nt++) {
                int off = (ncol0 + nt*8 + g4)*144 + koff;
                uint32_t bh2[2];
                bh2[0] = *(const uint32_t*)(sFh + off);
                bh2[1] = *(const uint32_t*)(sFh + off + 16);
                mma16816(sacc[nt], ah, bh2);
            }
        }
    }

    // residual + LN partial stats
    float sum0 = 0.f, sq0 = 0.f, sum1 = 0.f, sq1 = 0.f;
#pragma unroll
    for (int nt = 0; nt < 16; nt++) {
        int col = ncol0 + nt*8 + t4*2;
        float2 q0 = *(const float2*)(qin + (size_t)gr0*FF + col);
        float2 q1 = *(const float2*)(qin + (size_t)gr1*FF + col);
        sacc[nt][0] += q0.x; sacc[nt][1] += q0.y;
        sacc[nt][2] += q1.x; sacc[nt][3] += q1.y;
        sum0 += sacc[nt][0] + sacc[nt][1];
        sq0  += sacc[nt][0]*sacc[nt][0] + sacc[nt][1]*sacc[nt][1];
        sum1 += sacc[nt][2] + sacc[nt][3];
        sq1  += sacc[nt][2]*sacc[nt][2] + sacc[nt][3]*sacc[nt][3];
    }
    sum0 += __shfl_xor_sync(0xffffffffu, sum0, 1);
    sum0 += __shfl_xor_sync(0xffffffffu, sum0, 2);
    sq0  += __shfl_xor_sync(0xffffffffu, sq0, 1);
    sq0  += __shfl_xor_sync(0xffffffffu, sq0, 2);
    sum1 += __shfl_xor_sync(0xffffffffu, sum1, 1);
    sum1 += __shfl_xor_sync(0xffffffffu, sum1, 2);
    sq1  += __shfl_xor_sync(0xffffffffu, sq1, 1);
    sq1  += __shfl_xor_sync(0xffffffffu, sq1, 2);

    __syncthreads();
    if (t4 == 0) {
        red_s[r0][half] = sum0;     red_q[r0][half] = sq0;
        red_s[r0 + 8][half] = sum1; red_q[r0 + 8][half] = sq1;
    }
    __syncthreads();

    float s0 = red_s[r0][0] + red_s[r0][1];
    float qq0 = red_q[r0][0] + red_q[r0][1];
    float s1 = red_s[r0 + 8][0] + red_s[r0 + 8][1];
    float qq1 = red_q[r0 + 8][0] + red_q[r0 + 8][1];

    float mu0 = s0 * (1.f/256.f);
    float mu1 = s1 * (1.f/256.f);
    float rstd0 = rsqrtf(qq0 * (1.f/256.f) - mu0*mu0 + 1e-6f);
    float rstd1 = rsqrtf(qq1 * (1.f/256.f) - mu1*mu1 + 1e-6f);

#pragma unroll
    for (int nt = 0; nt < 16; nt++) {
        int col = ncol0 + nt*8 + t4*2;
        float2 g = *(const float2*)(lng + col);
        float2 bt = *(const float2*)(lnb + col);
        float2 o0, o1;
        o0.x = (sacc[nt][0] - mu0)*rstd0*g.x + bt.x;
        o0.y = (sacc[nt][1] - mu0)*rstd0*g.y + bt.y;
        o1.x = (sacc[nt][2] - mu1)*rstd1*g.x + bt.x;
        o1.y = (sacc[nt][3] - mu1)*rstd1*g.y + bt.y;
        *(float2*)(out + (size_t)gr0*FF + col) = o0;
        *(float2*)(out + (size_t)gr1*FF + col) = o1;
    }
}

// ---------------------------------------------------------------------------
extern "C" void kernel_launch(void* const* d_in, const int* in_sizes, int n_in,
                              void* d_out, int out_size)
{
    const float* q    = (const float*)d_in[0];
    const float* v    = (const float*)d_in[2];   // d_in[1] (k) unused by model
    const float* w_qs = (const float*)d_in[3];
    const float* w_vs = (const float*)d_in[4];
    const float* w1   = (const float*)d_in[5];
    const float* b1   = (const float*)d_in[6];
    const float* w2   = (const float*)d_in[7];
    const float* b2   = (const float*)d_in[8];
    const float* fcw  = (const float*)d_in[9];
    const float* lng  = (const float*)d_in[10];
    const float* lnb  = (const float*)d_in[11];
    float* out = (float*)d_out;

    cudaFuncSetAttribute(k_proj_mma,  cudaFuncAttributeMaxDynamicSharedMemorySize, PJ_SMEM);
    cudaFuncSetAttribute(k_final_mma, cudaFuncAttributeMaxDynamicSharedMemorySize, FN_SMEM);

    k_prep_all <<<912, 256>>>(w2, w_qs, w_vs, fcw, w1);
    k_proj_mma <<<dim3(250, HH, 2), 256, PJ_SMEM>>>(q, v, b1);
    k_attn_mma <<<dim3(4, HH, BB),  256>>>(b2);
    k_final_mma<<<500,              256, FN_SMEM>>>(q, lng, lnb, out);
}